// round 7
// baseline (speedup 1.0000x reference)
#include <cuda_runtime.h>
#include <cuda_bf16.h>
#include <math.h>
#include <stdint.h>
#include <stddef.h>

#define L 2048
#define C 512
#define CZ 16
#define H 16
#define D 32
#define EPS 1e-5f

#define SZ_CC (C * C)
#define SZ_W1 (C * 4 * C)
#define WR_TOT (4 * SZ_CC + 2 * SZ_W1)

// ---------------- scratch ----------------
__device__ float g_ss[4 * C];
__device__ float g_h[L * C];
__device__ float g_q[L * C];      // tf32-rounded, cols permuted within 8
__device__ float g_k[L * C];      // tf32-rounded, cols permuted within 8
__device__ float g_vT[C * L];     // tf32-rounded, [channel][token], token low-3 permuted
__device__ float g_wr[WR_TOT];    // W^T, tf32-rounded, k permuted within 8
__device__ __nv_bfloat16 g_bias16[(size_t)H * L * L];
__device__ float g_ao[L * C];
__device__ float g_x1[L * C];
__device__ float g_h2[L * C];
__device__ float g_ff[L * 4 * C];

// ---------------- helpers ----------------
__device__ __forceinline__ uint32_t f2tf(float f) {
    uint32_t u; asm("cvt.rna.tf32.f32 %0, %1;" : "=r"(u) : "f"(f)); return u;
}
__device__ __forceinline__ float rnd_tf(float f) { return __uint_as_float(f2tf(f)); }
__device__ __forceinline__ void mma8(float (&c)[4], const uint32_t (&a)[4],
                                     uint32_t b0, uint32_t b1) {
    asm volatile("mma.sync.aligned.m16n8k8.row.col.f32.tf32.tf32.f32 "
                 "{%0,%1,%2,%3},{%4,%5,%6,%7},{%8,%9},{%0,%1,%2,%3};"
                 : "+f"(c[0]), "+f"(c[1]), "+f"(c[2]), "+f"(c[3])
                 : "r"(a[0]), "r"(a[1]), "r"(a[2]), "r"(a[3]), "r"(b0), "r"(b1));
}
__device__ __forceinline__ uint32_t sptr(const void* p) {
    return (uint32_t)__cvta_generic_to_shared(p);
}
#define CPA16(dst, src) asm volatile("cp.async.cg.shared.global [%0], [%1], 16;" :: "r"(dst), "l"(src))
#define CP_COMMIT() asm volatile("cp.async.commit_group;")
#define CP_WAIT1() asm volatile("cp.async.wait_group 1;")
#define CP_WAIT0() asm volatile("cp.async.wait_group 0;")
// within-8 slot of index o:  o -> (o&3)*2 + (o>>2)   (maps qd,qd+4 -> 2qd,2qd+1)
__device__ __forceinline__ int permn(int n) {
    int o = n & 7; return (n & ~7) | ((o & 3) << 1) | (o >> 2);
}

// ---------------- condition projections ----------------
__global__ void ss_kernel(const float* __restrict__ cond,
                          const float* __restrict__ w1, const float* __restrict__ b1,
                          const float* __restrict__ w2, const float* __restrict__ b2) {
    int j = blockIdx.x * blockDim.x + threadIdx.x;
    if (j >= 4 * C) return;
    const float* w = (j < 2 * C) ? w1 : w2;
    const float* b = (j < 2 * C) ? b1 : b2;
    int jj = j & (2 * C - 1);
    float s = 0.f;
    for (int c = 0; c < C; c++) s += cond[c] * w[c * (2 * C) + jj];
    g_ss[j] = s + b[jj];
}

// ---------------- weight transpose + tf32 round + k-perm ----------------
// out[n][permk(k)] = rnd(W[k][n]);  32x32 tiles, 256 threads/block
__global__ __launch_bounds__(256) void wtrans_kernel(const float* __restrict__ Wq,
                                                     const float* __restrict__ Wk,
                                                     const float* __restrict__ Wv,
                                                     const float* __restrict__ Wo,
                                                     const float* __restrict__ W1,
                                                     const float* __restrict__ W2) {
    __shared__ float tile[32][33];
    int b = blockIdx.x;
    const float* src; float* dst; int K, N, tn, tb;
    if (b < 1024) {
        int mat = b >> 8; tb = b & 255;
        src = (mat == 0) ? Wq : (mat == 1) ? Wk : (mat == 2) ? Wv : Wo;
        dst = g_wr + (size_t)mat * SZ_CC; K = 512; N = 512; tn = 16;
    } else if (b < 2048) {
        src = W1; dst = g_wr + 4 * SZ_CC; K = 512; N = 2048; tn = 64; tb = b - 1024;
    } else {
        src = W2; dst = g_wr + 4 * SZ_CC + SZ_W1; K = 2048; N = 512; tn = 16; tb = b - 2048;
    }
    int k0 = (tb / tn) * 32, n0 = (tb % tn) * 32;
    int t = threadIdx.x;
    {
        int kk = t >> 3, nn = (t & 7) * 4;
        float4 v = *(const float4*)(src + (size_t)(k0 + kk) * N + n0 + nn);
        tile[kk][nn] = rnd_tf(v.x); tile[kk][nn + 1] = rnd_tf(v.y);
        tile[kk][nn + 2] = rnd_tf(v.z); tile[kk][nn + 3] = rnd_tf(v.w);
    }
    __syncthreads();
    {
        int nn = t >> 3, s4 = (t & 7) * 4;
        float4 ov;
        float* o = &ov.x;
        #pragma unroll
        for (int e = 0; e < 4; e++) {
            int s = s4 + e, s7 = s & 7;
            int ksrc = (s & ~7) | ((s7 >> 1) + ((s7 & 1) << 2));   // inverse perm
            o[e] = tile[ksrc][nn];
        }
        *(float4*)(dst + (size_t)(n0 + nn) * K + k0 + s4) = ov;
    }
}

// ---------------- adaLN ----------------
__global__ __launch_bounds__(256) void adaln_kernel(const float* __restrict__ x,
                                                    const float* __restrict__ g,
                                                    const float* __restrict__ b,
                                                    int ss_off, float* __restrict__ out) {
    int row = blockIdx.x;
    int t = threadIdx.x;
    const float* xr = x + (size_t)row * C;
    float v0 = xr[t], v1 = xr[t + 256];
    __shared__ float red[256];
    red[t] = v0 + v1;
    __syncthreads();
    for (int s = 128; s > 0; s >>= 1) { if (t < s) red[t] += red[t + s]; __syncthreads(); }
    float mu = red[0] * (1.0f / C);
    __syncthreads();
    float d0 = v0 - mu, d1 = v1 - mu;
    red[t] = d0 * d0 + d1 * d1;
    __syncthreads();
    for (int s = 128; s > 0; s >>= 1) { if (t < s) red[t] += red[t + s]; __syncthreads(); }
    float rs = rsqrtf(red[0] * (1.0f / C) + EPS);
    const float* scale = g_ss + ss_off;
    const float* shift = g_ss + ss_off + C;
    int c0 = t, c1 = t + 256;
    float o0 = (d0 * rs * g[c0] + b[c0]) * (1.f + scale[c0]) + shift[c0];
    float o1 = (d1 * rs * g[c1] + b[c1]) * (1.f + scale[c1]) + shift[c1];
    out[(size_t)row * C + c0] = rnd_tf(o0);
    out[(size_t)row * C + c1] = rnd_tf(o1);
}

// ---------------- pair bias precompute (bf16 out) ----------------
__global__ __launch_bounds__(256) void bias_kernel(const float* __restrict__ pair,
                                                   const float* __restrict__ Wpb) {
    __shared__ float w[CZ][H];
    int t = threadIdx.x;
    w[t >> 4][t & 15] = Wpb[t & 255];
    __syncthreads();
    size_t ij = (size_t)blockIdx.x * 256 + t;
    float p[CZ];
    const float* pp = pair + ij * CZ;
    #pragma unroll
    for (int z = 0; z < CZ; z++) p[z] = pp[z];
    #pragma unroll
    for (int h = 0; h < H; h++) {
        float b = 0.f;
        #pragma unroll
        for (int z = 0; z < CZ; z++) b += p[z] * w[z][h];
        g_bias16[(size_t)h * L * L + ij] = __float2bfloat16(b);
    }
}

// ---------------- tf32 MMA GEMM, cp.async 2-stage, W^T operand ----------------
// B is [n][k] with k permuted within 8 -> B-frag is one LDS.64 per nb.
// OUTMODE: 0 = plain, 1 = permn on n (for q/k), 2 = V transpose (vT[n][permrow(m)])
template <int NB, int HAS_BIAS, int HAS_RES, int ACT_GELU, int RND_OUT, int OUTMODE>
__device__ __forceinline__ void mma_gemm_body(const float* __restrict__ A,
                                              const float* __restrict__ B,
                                              const float* __restrict__ bias,
                                              const float* __restrict__ res,
                                              float* __restrict__ Cm,
                                              int N, int K, int bx, int by) {
    const int BN = NB * 16;
    __shared__ float As[2][128][20];
    __shared__ float Bs[2][BN][24];
    int t = threadIdx.x;
    int warp = t >> 5, lane = t & 31;
    int wm = warp >> 1, wn = warp & 1;
    int r = lane >> 2, qd = lane & 3;
    int row0 = by * 128, bn0 = bx * BN;

    float acc[2][NB][4];
    #pragma unroll
    for (int mi = 0; mi < 2; mi++)
        #pragma unroll
        for (int nb = 0; nb < NB; nb++)
            #pragma unroll
            for (int e = 0; e < 4; e++) acc[mi][nb][e] = 0.f;

    auto loadTiles = [&](int s, int k0) {
        #pragma unroll
        for (int c = 0; c < 2; c++) {
            int ch = t + c * 256;
            int m = ch >> 2, kq = (ch & 3) * 4;
            CPA16(sptr(&As[s][m][kq]), A + (size_t)(row0 + m) * K + k0 + kq);
        }
        if (NB == 8) {
            #pragma unroll
            for (int c = 0; c < 2; c++) {
                int ch = t + c * 256;
                int n = ch >> 2, kq = (ch & 3) * 4;
                CPA16(sptr(&Bs[s][n][kq]), B + (size_t)(bn0 + n) * K + k0 + kq);
            }
        } else {
            int n = t >> 2, kq = (t & 3) * 4;
            CPA16(sptr(&Bs[s][n][kq]), B + (size_t)(bn0 + n) * K + k0 + kq);
        }
        CP_COMMIT();
    };

    loadTiles(0, 0);
    int T = K >> 4;
    for (int it = 0; it < T; it++) {
        int s = it & 1;
        if (it + 1 < T) { loadTiles(s ^ 1, (it + 1) << 4); CP_WAIT1(); }
        else            { CP_WAIT0(); }
        __syncthreads();
        #pragma unroll
        for (int kk = 0; kk < 16; kk += 8) {
            uint32_t a[2][4];
            #pragma unroll
            for (int mi = 0; mi < 2; mi++) {
                int mo = wm * 32 + mi * 16 + r;
                a[mi][0] = __float_as_uint(As[s][mo][kk + qd]);
                a[mi][1] = __float_as_uint(As[s][mo + 8][kk + qd]);
                a[mi][2] = __float_as_uint(As[s][mo][kk + qd + 4]);
                a[mi][3] = __float_as_uint(As[s][mo + 8][kk + qd + 4]);
            }
            #pragma unroll
            for (int nb = 0; nb < NB; nb++) {
                int nc = wn * NB * 8 + nb * 8 + r;
                float2 bb = *(const float2*)&Bs[s][nc][kk + 2 * qd];
                mma8(acc[0][nb], a[0], __float_as_uint(bb.x), __float_as_uint(bb.y));
                mma8(acc[1][nb], a[1], __float_as_uint(bb.x), __float_as_uint(bb.y));
            }
        }
        __syncthreads();
    }

    #pragma unroll
    for (int mi = 0; mi < 2; mi++) {
        #pragma unroll
        for (int nb = 0; nb < NB; nb++) {
            int m = row0 + wm * 32 + mi * 16 + r;
            int n = bn0 + wn * NB * 8 + nb * 8 + 2 * qd;
            float v0 = acc[mi][nb][0], v1 = acc[mi][nb][1];
            float v2 = acc[mi][nb][2], v3 = acc[mi][nb][3];
            if (HAS_BIAS) {
                float b0 = bias[n], b1 = bias[n + 1];
                v0 += b0; v1 += b1; v2 += b0; v3 += b1;
            }
            if (ACT_GELU) {
                v0 = 0.5f * v0 * (1.0f + erff(v0 * 0.70710678118654752f));
                v1 = 0.5f * v1 * (1.0f + erff(v1 * 0.70710678118654752f));
                v2 = 0.5f * v2 * (1.0f + erff(v2 * 0.70710678118654752f));
                v3 = 0.5f * v3 * (1.0f + erff(v3 * 0.70710678118654752f));
            }
            if (HAS_RES) {
                float2 r0 = *(const float2*)(res + (size_t)m * N + n);
                float2 r1 = *(const float2*)(res + (size_t)(m + 8) * N + n);
                v0 += r0.x; v1 += r0.y; v2 += r1.x; v3 += r1.y;
            }
            if (RND_OUT) {
                v0 = rnd_tf(v0); v1 = rnd_tf(v1); v2 = rnd_tf(v2); v3 = rnd_tf(v3);
            }
            if (OUTMODE == 1) {
                int p0 = permn(n), p1 = permn(n + 1);
                Cm[(size_t)m * N + p0] = v0;
                Cm[(size_t)m * N + p1] = v1;
                Cm[(size_t)(m + 8) * N + p0] = v2;
                Cm[(size_t)(m + 8) * N + p1] = v3;
            } else if (OUTMODE == 2) {
                int pm = permn(m);   // token row permuted within 8
                Cm[(size_t)n * L + pm] = v0;
                Cm[(size_t)(n + 1) * L + pm] = v1;
                Cm[(size_t)n * L + pm + 8] = v2;
                Cm[(size_t)(n + 1) * L + pm + 8] = v3;
            } else {
                float2 o0 = {v0, v1}, o1 = {v2, v3};
                *(float2*)(Cm + (size_t)m * N + n) = o0;
                *(float2*)(Cm + (size_t)(m + 8) * N + n) = o1;
            }
        }
    }
}

__global__ __launch_bounds__(256) void qkv_mma(const float* __restrict__ hbuf,
                                               float* __restrict__ q,
                                               float* __restrict__ k,
                                               float* __restrict__ vT) {
    int sel = blockIdx.x >> 2, bxx = blockIdx.x & 3;
    const float* B = g_wr + (size_t)sel * SZ_CC;
    if (sel == 2)
        mma_gemm_body<8, 0, 0, 0, 1, 2>(hbuf, B, nullptr, nullptr, vT, C, C, bxx, blockIdx.y);
    else
        mma_gemm_body<8, 0, 0, 0, 1, 1>(hbuf, B, nullptr, nullptr, (sel == 0) ? q : k,
                                        C, C, bxx, blockIdx.y);
}

__global__ __launch_bounds__(256) void ffn1_mma(const float* __restrict__ A,
                                                const float* __restrict__ bias,
                                                float* __restrict__ Cm) {
    mma_gemm_body<8, 1, 0, 1, 1, 0>(A, g_wr + 4 * SZ_CC, bias, nullptr, Cm, 4 * C, C,
                                    blockIdx.x, blockIdx.y);
}

__global__ __launch_bounds__(256) void wo_mma(const float* __restrict__ A,
                                              const float* __restrict__ bias,
                                              const float* __restrict__ res,
                                              float* __restrict__ Cm) {
    mma_gemm_body<4, 1, 1, 0, 0, 0>(A, g_wr + 3 * SZ_CC, bias, res, Cm, C, C,
                                    blockIdx.x, blockIdx.y);
}

__global__ __launch_bounds__(256) void ffn2_mma(const float* __restrict__ A,
                                                const float* __restrict__ bias,
                                                const float* __restrict__ res,
                                                float* __restrict__ Cm) {
    mma_gemm_body<4, 1, 1, 0, 0, 0>(A, g_wr + 4 * SZ_CC + SZ_W1, bias, res, Cm, C, 4 * C,
                                    blockIdx.x, blockIdx.y);
}

// ---------------- flash attention ----------------
// smem (bytes):
//   Ks: [2][64][40] f32   @ 0       20480
//   Vs: [2][32][72] f32   @ 20480   18432   (vT rows: [d][j-permuted])
//   Bb: [2][128][72] bf16 @ 38912   36864
//   Ps: [8][16][72] f32   @ 75776   36864   (j-permuted slots)
#define FSMEM_BYTES 112640
__global__ __launch_bounds__(256, 2) void flash_kernel(const float* __restrict__ q,
                                                       const float* __restrict__ k,
                                                       const float* __restrict__ vT,
                                                       float* __restrict__ out) {
    extern __shared__ char fsm[];
    float* Ks = (float*)fsm;
    float* Vs = (float*)(fsm + 20480);
    __nv_bfloat16* Bb = (__nv_bfloat16*)(fsm + 38912);
    float* Ps = (float*)(fsm + 75776);

    int h = blockIdx.y;
    int i0 = blockIdx.x * 128;
    int hD = h * D;
    int t = threadIdx.x;
    int w = t >> 5, lane = t & 31;
    int r = lane >> 2, qd = lane & 3;
    int qrow0 = i0 + w * 16 + r;
    const __nv_bfloat16* Bh = g_bias16 + (size_t)h * L * L;

    auto loadKVB = [&](int s, int j0) {
        #pragma unroll
        for (int c = 0; c < 2; c++) {
            int ch = t + c * 256;
            int rw = ch >> 3, kq = (ch & 7) * 4;
            CPA16(sptr(&Ks[(s * 64 + rw) * 40 + kq]), k + (size_t)(j0 + rw) * C + hD + kq);
        }
        #pragma unroll
        for (int c = 0; c < 2; c++) {
            int ch = t + c * 256;
            int dd = ch >> 4, jq = (ch & 15) * 4;
            CPA16(sptr(&Vs[(s * 32 + dd) * 72 + jq]), vT + (size_t)(hD + dd) * L + j0 + jq);
        }
        #pragma unroll
        for (int c = 0; c < 4; c++) {
            int ch = t + c * 256;
            int rw = ch >> 3, e8 = (ch & 7) * 8;
            CPA16(sptr(&Bb[(s * 128 + rw) * 72 + e8]), Bh + (size_t)(i0 + rw) * L + j0 + e8);
        }
        CP_COMMIT();
    };

    loadKVB(0, 0);

    uint32_t qa[4][4];
    #pragma unroll
    for (int ks = 0; ks < 4; ks++) {
        float2 q0 = *(const float2*)(q + (size_t)qrow0 * C + hD + ks * 8 + 2 * qd);
        float2 q1 = *(const float2*)(q + (size_t)(qrow0 + 8) * C + hD + ks * 8 + 2 * qd);
        qa[ks][0] = __float_as_uint(q0.x);
        qa[ks][1] = __float_as_uint(q1.x);
        qa[ks][2] = __float_as_uint(q0.y);
        qa[ks][3] = __float_as_uint(q1.y);
    }

    float m0 = -1e30f, m1 = -1e30f, l0 = 0.f, l1 = 0.f;
    float o[4][4];
    #pragma unroll
    for (int nb = 0; nb < 4; nb++)
        #pragma unroll
        for (int e = 0; e < 4; e++) o[nb][e] = 0.f;

    const float sc = 0.17677669529663687f;
    int lr = w * 16 + r;
    // store slots for P (within-8 perm of columns 2qd, 2qd+1)
    int sp0 = permn(2 * qd), sp1 = permn(2 * qd + 1);

    for (int jt = 0; jt < L / 64; jt++) {
        int s = jt & 1;
        if (jt + 1 < L / 64) { loadKVB(s ^ 1, (jt + 1) * 64); CP_WAIT1(); }
        else                 { CP_WAIT0(); }
        __syncthreads();

        float sreg[8][4];
        #pragma unroll
        for (int nb = 0; nb < 8; nb++) {
            sreg[nb][0] = sreg[nb][1] = sreg[nb][2] = sreg[nb][3] = 0.f;
            #pragma unroll
            for (int ks = 0; ks < 4; ks++) {
                float2 kv = *(const float2*)&Ks[(s * 64 + nb * 8 + r) * 40 + ks * 8 + 2 * qd];
                mma8(sreg[nb], qa[ks], __float_as_uint(kv.x), __float_as_uint(kv.y));
            }
            float2 bb0 = __bfloat1622float2(
                *(const __nv_bfloat162*)&Bb[(s * 128 + lr) * 72 + nb * 8 + 2 * qd]);
            float2 bb1 = __bfloat1622float2(
                *(const __nv_bfloat162*)&Bb[(s * 128 + lr + 8) * 72 + nb * 8 + 2 * qd]);
            sreg[nb][0] = sreg[nb][0] * sc + bb0.x;
            sreg[nb][1] = sreg[nb][1] * sc + bb0.y;
            sreg[nb][2] = sreg[nb][2] * sc + bb1.x;
            sreg[nb][3] = sreg[nb][3] * sc + bb1.y;
        }

        float mx0 = -1e30f, mx1 = -1e30f;
        #pragma unroll
        for (int nb = 0; nb < 8; nb++) {
            mx0 = fmaxf(mx0, fmaxf(sreg[nb][0], sreg[nb][1]));
            mx1 = fmaxf(mx1, fmaxf(sreg[nb][2], sreg[nb][3]));
        }
        mx0 = fmaxf(mx0, __shfl_xor_sync(0xffffffffu, mx0, 1));
        mx0 = fmaxf(mx0, __shfl_xor_sync(0xffffffffu, mx0, 2));
        mx1 = fmaxf(mx1, __shfl_xor_sync(0xffffffffu, mx1, 1));
        mx1 = fmaxf(mx1, __shfl_xor_sync(0xffffffffu, mx1, 2));
        float mn0 = fmaxf(m0, mx0), mn1 = fmaxf(m1, mx1);
        float esc0 = __expf(m0 - mn0), esc1 = __expf(m1 - mn1);
        m0 = mn0; m1 = mn1;

        float sum0 = 0.f, sum1 = 0.f;
        #pragma unroll
        for (int nb = 0; nb < 8; nb++) {
            float p0 = __expf(sreg[nb][0] - mn0);
            float p1 = __expf(sreg[nb][1] - mn0);
            float p2 = __expf(sreg[nb][2] - mn1);
            float p3 = __expf(sreg[nb][3] - mn1);
            sum0 += p0 + p1; sum1 += p2 + p3;
            Ps[lr * 72 + nb * 8 + sp0] = p0;
            Ps[lr * 72 + nb * 8 + sp1] = p1;
            Ps[(lr + 8) * 72 + nb * 8 + sp0] = p2;
            Ps[(lr + 8) * 72 + nb * 8 + sp1] = p3;
        }
        sum0 += __shfl_xor_sync(0xffffffffu, sum0, 1);
        sum0 += __shfl_xor_sync(0xffffffffu, sum0, 2);
        sum1 += __shfl_xor_sync(0xffffffffu, sum1, 1);
        sum1 += __shfl_xor_sync(0xffffffffu, sum1, 2);
        l0 = l0 * esc0 + sum0;
        l1 = l1 * esc1 + sum1;

        #pragma unroll
        for (int nb = 0; nb < 4; nb++) {
            o[nb][0] *= esc0; o[nb][1] *= esc0;
            o[nb][2] *= esc1; o[nb][3] *= esc1;
        }
        __syncwarp();

        // P @ V : all fragments as LDS.64
        #pragma unroll
        for (int ks = 0; ks < 8; ks++) {
            float2 pa0 = *(const float2*)&Ps[lr * 72 + ks * 8 + 2 * qd];
            float2 pa1 = *(const float2*)&Ps[(lr + 8) * 72 + ks * 8 + 2 * qd];
            uint32_t pa[4];
            pa[0] = __float_as_uint(pa0.x);
            pa[1] = __float_as_uint(pa1.x);
            pa[2] = __float_as_uint(pa0.y);
            pa[3] = __float_as_uint(pa1.y);
            #pragma unroll
            for (int nbd = 0; nbd < 4; nbd++) {
                float2 vv = *(const float2*)&Vs[(s * 32 + nbd * 8 + r) * 72 + ks * 8 + 2 * qd];
                mma8(o[nbd], pa, __float_as_uint(vv.x), __float_as_uint(vv.y));
            }
        }
        __syncthreads();
    }

    float il0 = 1.0f / l0, il1 = 1.0f / l1;
    #pragma unroll
    for (int nbd = 0; nbd < 4; nbd++) {
        float2 w0 = {rnd_tf(o[nbd][0] * il0), rnd_tf(o[nbd][1] * il0)};
        float2 w1 = {rnd_tf(o[nbd][2] * il1), rnd_tf(o[nbd][3] * il1)};
        *(float2*)(out + (size_t)qrow0 * C + hD + nbd * 8 + 2 * qd) = w0;
        *(float2*)(out + (size_t)(qrow0 + 8) * C + hD + nbd * 8 + 2 * qd) = w1;
    }
}

// ---------------- launch ----------------
extern "C" void kernel_launch(void* const* d_in, const int* in_sizes, int n_in,
                              void* d_out, int out_size) {
    const float* x        = (const float*)d_in[0];
    const float* pair     = (const float*)d_in[1];
    const float* time_cond= (const float*)d_in[2];
    const float* ln1_g    = (const float*)d_in[3];
    const float* ln1_b    = (const float*)d_in[4];
    const float* ada1_w   = (const float*)d_in[5];
    const float* ada1_b   = (const float*)d_in[6];
    const float* Wq       = (const float*)d_in[7];
    const float* Wk       = (const float*)d_in[8];
    const float* Wv       = (const float*)d_in[9];
    const float* Wpb      = (const float*)d_in[10];
    const float* Wo       = (const float*)d_in[11];
    const float* bo       = (const float*)d_in[12];
    const float* ln2_g    = (const float*)d_in[13];
    const float* ln2_b    = (const float*)d_in[14];
    const float* ada2_w   = (const float*)d_in[15];
    const float* ada2_b   = (const float*)d_in[16];
    const float* W1       = (const float*)d_in[17];
    const float* b1       = (const float*)d_in[18];
    const float* W2       = (const float*)d_in[19];
    const float* b2       = (const float*)d_in[20];
    float* out = (float*)d_out;

    float *p_h, *p_q, *p_k, *p_vT, *p_ao, *p_x1, *p_h2, *p_ff;
    cudaGetSymbolAddress((void**)&p_h,  g_h);
    cudaGetSymbolAddress((void**)&p_q,  g_q);
    cudaGetSymbolAddress((void**)&p_k,  g_k);
    cudaGetSymbolAddress((void**)&p_vT, g_vT);
    cudaGetSymbolAddress((void**)&p_ao, g_ao);
    cudaGetSymbolAddress((void**)&p_x1, g_x1);
    cudaGetSymbolAddress((void**)&p_h2, g_h2);
    cudaGetSymbolAddress((void**)&p_ff, g_ff);

    static cudaStream_t s1;
    static cudaEvent_t e0, e1;
    static int init_done = 0;
    if (!init_done) {
        cudaFuncSetAttribute(flash_kernel,
                             cudaFuncAttributeMaxDynamicSharedMemorySize, FSMEM_BYTES);
        cudaStreamCreateWithFlags(&s1, cudaStreamNonBlocking);
        cudaEventCreateWithFlags(&e0, cudaEventDisableTiming);
        cudaEventCreateWithFlags(&e1, cudaEventDisableTiming);
        init_done = 1;
    }

    // fork: bias (memory-bound) runs concurrently with the compute chain
    cudaEventRecord(e0, 0);
    cudaStreamWaitEvent(s1, e0, 0);
    bias_kernel<<<(L * L) / 256, 256, 0, s1>>>(pair, Wpb);
    cudaEventRecord(e1, s1);

    ss_kernel<<<8, 256>>>(time_cond, ada1_w, ada1_b, ada2_w, ada2_b);
    wtrans_kernel<<<3072, 256>>>(Wq, Wk, Wv, Wo, W1, W2);
    adaln_kernel<<<L, 256>>>(x, ln1_g, ln1_b, 0, p_h);
    qkv_mma<<<dim3(12, 16), 256>>>(p_h, p_q, p_k, p_vT);

    // join before flash (needs g_bias16)
    cudaStreamWaitEvent(0, e1, 0);
    flash_kernel<<<dim3(L / 128, H), 256, FSMEM_BYTES>>>(p_q, p_k, p_vT, p_ao);

    wo_mma<<<dim3(8, 16), 256>>>(p_ao, bo, x, p_x1);
    adaln_kernel<<<L, 256>>>(p_x1, ln2_g, ln2_b, 2 * C, p_h2);
    ffn1_mma<<<dim3(16, 16), 256>>>(p_h2, b1, p_ff);
    ffn2_mma<<<dim3(8, 16), 256>>>(p_ff, b2, p_x1, out);
}

// round 8
// speedup vs baseline: 1.0219x; 1.0219x over previous
#include <cuda_runtime.h>
#include <cuda_bf16.h>
#include <math.h>
#include <stdint.h>
#include <stddef.h>

#define L 2048
#define C 512
#define CZ 16
#define H 16
#define D 32
#define EPS 1e-5f

#define SZ_CC (C * C)          // 262144
#define SZ_W1 (C * 4 * C)      // 1048576
#define WR_TOT (4 * SZ_CC + 2 * SZ_W1)   // 3145728 floats

// ---------------- scratch ----------------
__device__ float g_ss[4 * C];
__device__ float g_h[L * C];
__device__ float g_q[L * C];      // tf32-rounded, cols permuted within 8
__device__ float g_k[L * C];      // tf32-rounded, cols permuted within 8
__device__ float g_v[L * C];      // tf32-rounded
__device__ float g_wr[WR_TOT];    // tf32-rounded weights
__device__ __nv_bfloat16 g_bias16[(size_t)H * L * L];
__device__ float g_ao[L * C];
__device__ float g_x1[L * C];
__device__ float g_h2[L * C];
__device__ float g_ff[L * 4 * C];

// ---------------- helpers ----------------
__device__ __forceinline__ uint32_t f2tf(float f) {
    uint32_t u; asm("cvt.rna.tf32.f32 %0, %1;" : "=r"(u) : "f"(f)); return u;
}
__device__ __forceinline__ float rnd_tf(float f) { return __uint_as_float(f2tf(f)); }
__device__ __forceinline__ void mma8(float (&c)[4], const uint32_t (&a)[4],
                                     uint32_t b0, uint32_t b1) {
    asm volatile("mma.sync.aligned.m16n8k8.row.col.f32.tf32.tf32.f32 "
                 "{%0,%1,%2,%3},{%4,%5,%6,%7},{%8,%9},{%0,%1,%2,%3};"
                 : "+f"(c[0]), "+f"(c[1]), "+f"(c[2]), "+f"(c[3])
                 : "r"(a[0]), "r"(a[1]), "r"(a[2]), "r"(a[3]), "r"(b0), "r"(b1));
}
__device__ __forceinline__ uint32_t sptr(const void* p) {
    return (uint32_t)__cvta_generic_to_shared(p);
}
#define CPA16(dst, src) asm volatile("cp.async.cg.shared.global [%0], [%1], 16;" :: "r"(dst), "l"(src))
#define CP_COMMIT() asm volatile("cp.async.commit_group;")
#define CP_WAIT1() asm volatile("cp.async.wait_group 1;")
#define CP_WAIT0() asm volatile("cp.async.wait_group 0;")
// permute col within 8: old o -> (o&3)*2 + (o>>2); maps (qd, qd+4) -> (2qd, 2qd+1)
__device__ __forceinline__ int permn(int n) {
    int o = n & 7; return (n & ~7) | ((o & 3) << 1) | (o >> 2);
}

// ---------------- condition projections ----------------
__global__ void ss_kernel(const float* __restrict__ cond,
                          const float* __restrict__ w1, const float* __restrict__ b1,
                          const float* __restrict__ w2, const float* __restrict__ b2) {
    int j = blockIdx.x * blockDim.x + threadIdx.x;
    if (j >= 4 * C) return;
    const float* w = (j < 2 * C) ? w1 : w2;
    const float* b = (j < 2 * C) ? b1 : b2;
    int jj = j & (2 * C - 1);
    float s = 0.f;
    for (int c = 0; c < C; c++) s += cond[c] * w[c * (2 * C) + jj];
    g_ss[j] = s + b[jj];
}

// ---------------- weight tf32 pre-round ----------------
__global__ __launch_bounds__(256) void wround_kernel(const float* __restrict__ Wq,
                                                     const float* __restrict__ Wk,
                                                     const float* __restrict__ Wv,
                                                     const float* __restrict__ Wo,
                                                     const float* __restrict__ W1,
                                                     const float* __restrict__ W2) {
    size_t i = ((size_t)blockIdx.x * 256 + threadIdx.x) * 4;
    const float* src; size_t off;
    if (i < SZ_CC)                    { src = Wq; off = i; }
    else if (i < 2 * (size_t)SZ_CC)   { src = Wk; off = i - SZ_CC; }
    else if (i < 3 * (size_t)SZ_CC)   { src = Wv; off = i - 2 * SZ_CC; }
    else if (i < 4 * (size_t)SZ_CC)   { src = Wo; off = i - 3 * SZ_CC; }
    else if (i < 4 * (size_t)SZ_CC + SZ_W1) { src = W1; off = i - 4 * SZ_CC; }
    else                              { src = W2; off = i - 4 * SZ_CC - SZ_W1; }
    float4 v = *(const float4*)(src + off);
    float4 o;
    o.x = rnd_tf(v.x); o.y = rnd_tf(v.y); o.z = rnd_tf(v.z); o.w = rnd_tf(v.w);
    *(float4*)(g_wr + i) = o;
}

// ---------------- adaLN ----------------
__global__ __launch_bounds__(256) void adaln_kernel(const float* __restrict__ x,
                                                    const float* __restrict__ g,
                                                    const float* __restrict__ b,
                                                    int ss_off, float* __restrict__ out) {
    int row = blockIdx.x;
    int t = threadIdx.x;
    const float* xr = x + (size_t)row * C;
    float v0 = xr[t], v1 = xr[t + 256];
    __shared__ float red[256];
    red[t] = v0 + v1;
    __syncthreads();
    for (int s = 128; s > 0; s >>= 1) { if (t < s) red[t] += red[t + s]; __syncthreads(); }
    float mu = red[0] * (1.0f / C);
    __syncthreads();
    float d0 = v0 - mu, d1 = v1 - mu;
    red[t] = d0 * d0 + d1 * d1;
    __syncthreads();
    for (int s = 128; s > 0; s >>= 1) { if (t < s) red[t] += red[t + s]; __syncthreads(); }
    float rs = rsqrtf(red[0] * (1.0f / C) + EPS);
    const float* scale = g_ss + ss_off;
    const float* shift = g_ss + ss_off + C;
    int c0 = t, c1 = t + 256;
    float o0 = (d0 * rs * g[c0] + b[c0]) * (1.f + scale[c0]) + shift[c0];
    float o1 = (d1 * rs * g[c1] + b[c1]) * (1.f + scale[c1]) + shift[c1];
    out[(size_t)row * C + c0] = rnd_tf(o0);
    out[(size_t)row * C + c1] = rnd_tf(o1);
}

// ---------------- pair bias precompute (bf16 out) ----------------
__global__ __launch_bounds__(256) void bias_kernel(const float* __restrict__ pair,
                                                   const float* __restrict__ Wpb) {
    __shared__ float w[CZ][H];
    int t = threadIdx.x;
    w[t >> 4][t & 15] = Wpb[t & 255];
    __syncthreads();
    size_t ij = (size_t)blockIdx.x * 256 + t;
    float p[CZ];
    const float* pp = pair + ij * CZ;
    #pragma unroll
    for (int z = 0; z < CZ; z++) p[z] = pp[z];
    #pragma unroll
    for (int h = 0; h < H; h++) {
        float b = 0.f;
        #pragma unroll
        for (int z = 0; z < CZ; z++) b += p[z] * w[z][h];
        g_bias16[(size_t)h * L * L + ij] = __float2bfloat16(b);
    }
}

// ---------------- tf32 MMA GEMM, cp.async 2-stage ----------------
// BM=128, BN=NB*16, BK=16. 256 threads = 8 warps (4m x 2n), warp tile 32 x NB*8.
// A, B pre-rounded tf32 in gmem; no cvt inside.
template <int NB, int HAS_BIAS, int HAS_RES, int ACT_GELU, int RND_OUT>
__device__ __forceinline__ void mma_gemm_body(const float* __restrict__ A,
                                              const float* __restrict__ B,
                                              const float* __restrict__ bias,
                                              const float* __restrict__ res,
                                              float* __restrict__ Cm,
                                              int N, int K, int bx, int by, int permqk) {
    const int BN = NB * 16;
    __shared__ float As[2][128][20];
    __shared__ float Bs[2][16][BN + 8];
    int t = threadIdx.x;
    int warp = t >> 5, lane = t & 31;
    int wm = warp >> 1, wn = warp & 1;
    int r = lane >> 2, qd = lane & 3;
    int row0 = by * 128, bn0 = bx * BN;

    float acc[2][NB][4];
    #pragma unroll
    for (int mi = 0; mi < 2; mi++)
        #pragma unroll
        for (int nb = 0; nb < NB; nb++)
            #pragma unroll
            for (int e = 0; e < 4; e++) acc[mi][nb][e] = 0.f;

    auto loadTiles = [&](int s, int k0) {
        #pragma unroll
        for (int c = 0; c < 2; c++) {
            int ch = t + c * 256;
            int m = ch >> 2, kq = (ch & 3) * 4;
            CPA16(sptr(&As[s][m][kq]), A + (size_t)(row0 + m) * K + k0 + kq);
        }
        if (NB == 8) {
            #pragma unroll
            for (int c = 0; c < 2; c++) {
                int ch = t + c * 256;
                int kk = ch >> 5, n4 = (ch & 31) * 4;
                CPA16(sptr(&Bs[s][kk][n4]), B + (size_t)(k0 + kk) * N + bn0 + n4);
            }
        } else {
            int kk = t >> 4, n4 = (t & 15) * 4;
            CPA16(sptr(&Bs[s][kk][n4]), B + (size_t)(k0 + kk) * N + bn0 + n4);
        }
        CP_COMMIT();
    };

    loadTiles(0, 0);
    int T = K >> 4;
    for (int it = 0; it < T; it++) {
        int s = it & 1;
        if (it + 1 < T) { loadTiles(s ^ 1, (it + 1) << 4); CP_WAIT1(); }
        else            { CP_WAIT0(); }
        __syncthreads();
        #pragma unroll
        for (int kk = 0; kk < 16; kk += 8) {
            uint32_t a[2][4];
            #pragma unroll
            for (int mi = 0; mi < 2; mi++) {
                int mo = wm * 32 + mi * 16 + r;
                a[mi][0] = __float_as_uint(As[s][mo][kk + qd]);
                a[mi][1] = __float_as_uint(As[s][mo + 8][kk + qd]);
                a[mi][2] = __float_as_uint(As[s][mo][kk + qd + 4]);
                a[mi][3] = __float_as_uint(As[s][mo + 8][kk + qd + 4]);
            }
            #pragma unroll
            for (int nb = 0; nb < NB; nb++) {
                int nc = wn * NB * 8 + nb * 8 + r;
                uint32_t b0 = __float_as_uint(Bs[s][kk + qd][nc]);
                uint32_t b1 = __float_as_uint(Bs[s][kk + qd + 4][nc]);
                mma8(acc[0][nb], a[0], b0, b1);
                mma8(acc[1][nb], a[1], b0, b1);
            }
        }
        __syncthreads();
    }

    #pragma unroll
    for (int mi = 0; mi < 2; mi++) {
        #pragma unroll
        for (int nb = 0; nb < NB; nb++) {
            int m = row0 + wm * 32 + mi * 16 + r;
            int n = bn0 + wn * NB * 8 + nb * 8 + 2 * qd;
            float v0 = acc[mi][nb][0], v1 = acc[mi][nb][1];
            float v2 = acc[mi][nb][2], v3 = acc[mi][nb][3];
            if (HAS_BIAS) {
                float b0 = bias[n], b1 = bias[n + 1];
                v0 += b0; v1 += b1; v2 += b0; v3 += b1;
            }
            if (ACT_GELU) {
                v0 = 0.5f * v0 * (1.0f + erff(v0 * 0.70710678118654752f));
                v1 = 0.5f * v1 * (1.0f + erff(v1 * 0.70710678118654752f));
                v2 = 0.5f * v2 * (1.0f + erff(v2 * 0.70710678118654752f));
                v3 = 0.5f * v3 * (1.0f + erff(v3 * 0.70710678118654752f));
            }
            if (HAS_RES) {
                float2 r0 = *(const float2*)(res + (size_t)m * N + n);
                float2 r1 = *(const float2*)(res + (size_t)(m + 8) * N + n);
                v0 += r0.x; v1 += r0.y; v2 += r1.x; v3 += r1.y;
            }
            if (RND_OUT) {
                v0 = rnd_tf(v0); v1 = rnd_tf(v1); v2 = rnd_tf(v2); v3 = rnd_tf(v3);
            }
            if (permqk) {
                int p0 = permn(n), p1 = permn(n + 1);
                Cm[(size_t)m * N + p0] = v0;
                Cm[(size_t)m * N + p1] = v1;
                Cm[(size_t)(m + 8) * N + p0] = v2;
                Cm[(size_t)(m + 8) * N + p1] = v3;
            } else {
                float2 o0 = {v0, v1}, o1 = {v2, v3};
                *(float2*)(Cm + (size_t)m * N + n) = o0;
                *(float2*)(Cm + (size_t)(m + 8) * N + n) = o1;
            }
        }
    }
}

__global__ __launch_bounds__(256) void qkv_mma(const float* __restrict__ hbuf,
                                               float* __restrict__ q,
                                               float* __restrict__ k,
                                               float* __restrict__ v) {
    int sel = blockIdx.x >> 2, bxx = blockIdx.x & 3;
    const float* B = g_wr + (size_t)sel * SZ_CC;
    float* O = (sel == 0) ? q : (sel == 1) ? k : v;
    mma_gemm_body<8, 0, 0, 0, 1>(hbuf, B, nullptr, nullptr, O, C, C, bxx, blockIdx.y,
                                 sel != 2);
}

__global__ __launch_bounds__(256) void ffn1_mma(const float* __restrict__ A,
                                                const float* __restrict__ bias,
                                                float* __restrict__ Cm) {
    mma_gemm_body<8, 1, 0, 1, 1>(A, g_wr + 4 * SZ_CC, bias, nullptr, Cm, 4 * C, C,
                                 blockIdx.x, blockIdx.y, 0);
}

__global__ __launch_bounds__(256) void wo_mma(const float* __restrict__ A,
                                              const float* __restrict__ bias,
                                              const float* __restrict__ res,
                                              float* __restrict__ Cm) {
    mma_gemm_body<4, 1, 1, 0, 0>(A, g_wr + 3 * SZ_CC, bias, res, Cm, C, C,
                                 blockIdx.x, blockIdx.y, 0);
}

__global__ __launch_bounds__(256) void ffn2_mma(const float* __restrict__ A,
                                                const float* __restrict__ bias,
                                                const float* __restrict__ res,
                                                float* __restrict__ Cm) {
    mma_gemm_body<4, 1, 1, 0, 0>(A, g_wr + 4 * SZ_CC + SZ_W1, bias, res, Cm, C, 4 * C,
                                 blockIdx.x, blockIdx.y, 0);
}

// ---------------- flash attention: 128 q-rows, 256 threads, cp.async double buffer ----
// dynamic smem layout (bytes):
//   Ks: [2][64][40] f32      @ 0       size 20480
//   Vs: [2][64][40] f32      @ 20480   size 20480
//   Bb: [2][128][72] bf16    @ 40960   size 36864
//   Ps: [8][16][72] f32      @ 77824   size 36864
#define FSMEM_BYTES 114688
__global__ __launch_bounds__(256, 2) void flash_kernel(const float* __restrict__ q,
                                                       const float* __restrict__ k,
                                                       const float* __restrict__ v,
                                                       float* __restrict__ out) {
    extern __shared__ char fsm[];
    float* Ks = (float*)fsm;
    float* Vs = (float*)(fsm + 20480);
    __nv_bfloat16* Bb = (__nv_bfloat16*)(fsm + 40960);
    float* Ps = (float*)(fsm + 77824);

    int h = blockIdx.y;
    int i0 = blockIdx.x * 128;
    int hD = h * D;
    int t = threadIdx.x;
    int w = t >> 5, lane = t & 31;
    int r = lane >> 2, qd = lane & 3;
    int qrow0 = i0 + w * 16 + r;
    const __nv_bfloat16* Bh = g_bias16 + (size_t)h * L * L;

    auto loadKVB = [&](int s, int j0) {
        #pragma unroll
        for (int c = 0; c < 2; c++) {
            int ch = t + c * 256;
            int rw = ch >> 3, kq = (ch & 7) * 4;
            CPA16(sptr(&Ks[(s * 64 + rw) * 40 + kq]), k + (size_t)(j0 + rw) * C + hD + kq);
            CPA16(sptr(&Vs[(s * 64 + rw) * 40 + kq]), v + (size_t)(j0 + rw) * C + hD + kq);
        }
        #pragma unroll
        for (int c = 0; c < 4; c++) {
            int ch = t + c * 256;
            int rw = ch >> 3, e8 = (ch & 7) * 8;
            CPA16(sptr(&Bb[(s * 128 + rw) * 72 + e8]), Bh + (size_t)(i0 + rw) * L + j0 + e8);
        }
        CP_COMMIT();
    };

    loadKVB(0, 0);

    // Q fragments: permuted cols -> float2 gives (old qd, old qd+4)
    uint32_t qa[4][4];
    #pragma unroll
    for (int ks = 0; ks < 4; ks++) {
        float2 q0 = *(const float2*)(q + (size_t)qrow0 * C + hD + ks * 8 + 2 * qd);
        float2 q1 = *(const float2*)(q + (size_t)(qrow0 + 8) * C + hD + ks * 8 + 2 * qd);
        qa[ks][0] = __float_as_uint(q0.x);
        qa[ks][1] = __float_as_uint(q1.x);
        qa[ks][2] = __float_as_uint(q0.y);
        qa[ks][3] = __float_as_uint(q1.y);
    }

    float m0 = -1e30f, m1 = -1e30f, l0 = 0.f, l1 = 0.f;
    float o[4][4];
    #pragma unroll
    for (int nb = 0; nb < 4; nb++)
        #pragma unroll
        for (int e = 0; e < 4; e++) o[nb][e] = 0.f;

    const float sc = 0.17677669529663687f;   // 1/sqrt(32)
    int lr = w * 16 + r;

    for (int jt = 0; jt < L / 64; jt++) {
        int s = jt & 1;
        if (jt + 1 < L / 64) { loadKVB(s ^ 1, (jt + 1) * 64); CP_WAIT1(); }
        else                 { CP_WAIT0(); }
        __syncthreads();

        // QK^T + bias
        float sreg[8][4];
        #pragma unroll
        for (int nb = 0; nb < 8; nb++) {
            sreg[nb][0] = sreg[nb][1] = sreg[nb][2] = sreg[nb][3] = 0.f;
            #pragma unroll
            for (int ks = 0; ks < 4; ks++) {
                float2 kv = *(const float2*)&Ks[(s * 64 + nb * 8 + r) * 40 + ks * 8 + 2 * qd];
                mma8(sreg[nb], qa[ks], __float_as_uint(kv.x), __float_as_uint(kv.y));
            }
            float2 bb0 = __bfloat1622float2(
                *(const __nv_bfloat162*)&Bb[(s * 128 + lr) * 72 + nb * 8 + 2 * qd]);
            float2 bb1 = __bfloat1622float2(
                *(const __nv_bfloat162*)&Bb[(s * 128 + lr + 8) * 72 + nb * 8 + 2 * qd]);
            sreg[nb][0] = sreg[nb][0] * sc + bb0.x;
            sreg[nb][1] = sreg[nb][1] * sc + bb0.y;
            sreg[nb][2] = sreg[nb][2] * sc + bb1.x;
            sreg[nb][3] = sreg[nb][3] * sc + bb1.y;
        }

        // online softmax
        float mx0 = -1e30f, mx1 = -1e30f;
        #pragma unroll
        for (int nb = 0; nb < 8; nb++) {
            mx0 = fmaxf(mx0, fmaxf(sreg[nb][0], sreg[nb][1]));
            mx1 = fmaxf(mx1, fmaxf(sreg[nb][2], sreg[nb][3]));
        }
        mx0 = fmaxf(mx0, __shfl_xor_sync(0xffffffffu, mx0, 1));
        mx0 = fmaxf(mx0, __shfl_xor_sync(0xffffffffu, mx0, 2));
        mx1 = fmaxf(mx1, __shfl_xor_sync(0xffffffffu, mx1, 1));
        mx1 = fmaxf(mx1, __shfl_xor_sync(0xffffffffu, mx1, 2));
        float mn0 = fmaxf(m0, mx0), mn1 = fmaxf(m1, mx1);
        float esc0 = __expf(m0 - mn0), esc1 = __expf(m1 - mn1);
        m0 = mn0; m1 = mn1;

        float sum0 = 0.f, sum1 = 0.f;
        #pragma unroll
        for (int nb = 0; nb < 8; nb++) {
            float p0 = __expf(sreg[nb][0] - mn0);
            float p1 = __expf(sreg[nb][1] - mn0);
            float p2 = __expf(sreg[nb][2] - mn1);
            float p3 = __expf(sreg[nb][3] - mn1);
            sum0 += p0 + p1; sum1 += p2 + p3;
            float2 w0 = {p0, p1}, w1 = {p2, p3};
            *(float2*)&Ps[(w * 16 + r) * 72 + nb * 8 + 2 * qd] = w0;
            *(float2*)&Ps[(w * 16 + r + 8) * 72 + nb * 8 + 2 * qd] = w1;
        }
        sum0 += __shfl_xor_sync(0xffffffffu, sum0, 1);
        sum0 += __shfl_xor_sync(0xffffffffu, sum0, 2);
        sum1 += __shfl_xor_sync(0xffffffffu, sum1, 1);
        sum1 += __shfl_xor_sync(0xffffffffu, sum1, 2);
        l0 = l0 * esc0 + sum0;
        l1 = l1 * esc1 + sum1;

        #pragma unroll
        for (int nb = 0; nb < 4; nb++) {
            o[nb][0] *= esc0; o[nb][1] *= esc0;
            o[nb][2] *= esc1; o[nb][3] *= esc1;
        }
        __syncwarp();

        // P @ V
        #pragma unroll
        for (int ks = 0; ks < 8; ks++) {
            uint32_t pa[4];
            pa[0] = __float_as_uint(Ps[(w * 16 + r) * 72 + ks * 8 + qd]);
            pa[1] = __float_as_uint(Ps[(w * 16 + r + 8) * 72 + ks * 8 + qd]);
            pa[2] = __float_as_uint(Ps[(w * 16 + r) * 72 + ks * 8 + qd + 4]);
            pa[3] = __float_as_uint(Ps[(w * 16 + r + 8) * 72 + ks * 8 + qd + 4]);
            #pragma unroll
            for (int nbd = 0; nbd < 4; nbd++) {
                uint32_t vb0 = __float_as_uint(Vs[(s * 64 + ks * 8 + qd) * 40 + nbd * 8 + r]);
                uint32_t vb1 = __float_as_uint(Vs[(s * 64 + ks * 8 + qd + 4) * 40 + nbd * 8 + r]);
                mma8(o[nbd], pa, vb0, vb1);
            }
        }
        __syncthreads();
    }

    float il0 = 1.0f / l0, il1 = 1.0f / l1;
    #pragma unroll
    for (int nbd = 0; nbd < 4; nbd++) {
        float2 w0 = {rnd_tf(o[nbd][0] * il0), rnd_tf(o[nbd][1] * il0)};
        float2 w1 = {rnd_tf(o[nbd][2] * il1), rnd_tf(o[nbd][3] * il1)};
        *(float2*)(out + (size_t)qrow0 * C + hD + nbd * 8 + 2 * qd) = w0;
        *(float2*)(out + (size_t)(qrow0 + 8) * C + hD + nbd * 8 + 2 * qd) = w1;
    }
}

// ---------------- launch ----------------
extern "C" void kernel_launch(void* const* d_in, const int* in_sizes, int n_in,
                              void* d_out, int out_size) {
    const float* x        = (const float*)d_in[0];
    const float* pair     = (const float*)d_in[1];
    const float* time_cond= (const float*)d_in[2];
    const float* ln1_g    = (const float*)d_in[3];
    const float* ln1_b    = (const float*)d_in[4];
    const float* ada1_w   = (const float*)d_in[5];
    const float* ada1_b   = (const float*)d_in[6];
    const float* Wq       = (const float*)d_in[7];
    const float* Wk       = (const float*)d_in[8];
    const float* Wv       = (const float*)d_in[9];
    const float* Wpb      = (const float*)d_in[10];
    const float* Wo       = (const float*)d_in[11];
    const float* bo       = (const float*)d_in[12];
    const float* ln2_g    = (const float*)d_in[13];
    const float* ln2_b    = (const float*)d_in[14];
    const float* ada2_w   = (const float*)d_in[15];
    const float* ada2_b   = (const float*)d_in[16];
    const float* W1       = (const float*)d_in[17];
    const float* b1       = (const float*)d_in[18];
    const float* W2       = (const float*)d_in[19];
    const float* b2       = (const float*)d_in[20];
    float* out = (float*)d_out;

    float *p_h, *p_q, *p_k, *p_v, *p_ao, *p_x1, *p_h2, *p_ff;
    cudaGetSymbolAddress((void**)&p_h,  g_h);
    cudaGetSymbolAddress((void**)&p_q,  g_q);
    cudaGetSymbolAddress((void**)&p_k,  g_k);
    cudaGetSymbolAddress((void**)&p_v,  g_v);
    cudaGetSymbolAddress((void**)&p_ao, g_ao);
    cudaGetSymbolAddress((void**)&p_x1, g_x1);
    cudaGetSymbolAddress((void**)&p_h2, g_h2);
    cudaGetSymbolAddress((void**)&p_ff, g_ff);

    static cudaStream_t s1;
    static cudaEvent_t e0, e1;
    static int init_done = 0;
    if (!init_done) {
        cudaFuncSetAttribute(flash_kernel,
                             cudaFuncAttributeMaxDynamicSharedMemorySize, FSMEM_BYTES);
        cudaStreamCreateWithFlags(&s1, cudaStreamNonBlocking);
        cudaEventCreateWithFlags(&e0, cudaEventDisableTiming);
        cudaEventCreateWithFlags(&e1, cudaEventDisableTiming);
        init_done = 1;
    }

    // fork: bias (HBM-bound, independent) overlaps the compute prologue chain
    cudaEventRecord(e0, 0);
    cudaStreamWaitEvent(s1, e0, 0);
    bias_kernel<<<(L * L) / 256, 256, 0, s1>>>(pair, Wpb);
    cudaEventRecord(e1, s1);

    ss_kernel<<<8, 256>>>(time_cond, ada1_w, ada1_b, ada2_w, ada2_b);
    wround_kernel<<<WR_TOT / 1024, 256>>>(Wq, Wk, Wv, Wo, W1, W2);
    adaln_kernel<<<L, 256>>>(x, ln1_g, ln1_b, 0, p_h);
    qkv_mma<<<dim3(12, 16), 256>>>(p_h, p_q, p_k, p_v);

    // join before flash (needs g_bias16)
    cudaStreamWaitEvent(0, e1, 0);
    flash_kernel<<<dim3(L / 128, H), 256, FSMEM_BYTES>>>(p_q, p_k, p_v, p_ao);

    wo_mma<<<dim3(8, 16), 256>>>(p_ao, bo, x, p_x1);
    adaln_kernel<<<L, 256>>>(p_x1, ln2_g, ln2_b, 2 * C, p_h2);
    ffn1_mma<<<dim3(16, 16), 256>>>(p_h2, b1, p_ff);
    ffn2_mma<<<dim3(8, 16), 256>>>(p_ff, b2, p_x1, out);
}

// round 13
// speedup vs baseline: 1.2863x; 1.2588x over previous
#include <cuda_runtime.h>
#include <cuda_fp16.h>
#include <cuda_bf16.h>
#include <math.h>
#include <stdint.h>
#include <stddef.h>

#define L 2048
#define C 512
#define CZ 16
#define H 16
#define D 32
#define EPS 1e-5f

// u32 (half2-pair) sizes of packed weights
#define U_CC 131072              // 512*512/2
#define U_W1 524288              // 512*2048/2
#define U_W2 524288              // 2048*512/2
#define WP_TOT (4 * U_CC + U_W1 + U_W2)

// ---------------- scratch ----------------
__device__ float g_ss[4 * C];
__device__ __half g_h[L * C];
__device__ __half g_q[L * C];
__device__ __half g_k[L * C];
__device__ uint32_t g_vp[C * (L / 2)];     // [channel][token-pair] half2 (tok, tok+8)
__device__ uint32_t g_wp[WP_TOT];          // packed weights [k/2][n] half2
__device__ __nv_bfloat16 g_bias16[(size_t)H * L * L];  // slot-permuted j
__device__ __half g_ao[L * C];
__device__ float g_x1[L * C];
__device__ __half g_h2[L * C];
__device__ __half g_ff[L * 4 * C];

// ---------------- helpers ----------------
__device__ __forceinline__ uint32_t packh2(float lo, float hi) {
    __half2 h = __floats2half2_rn(lo, hi);
    return *(uint32_t*)&h;
}
__device__ __forceinline__ void mma16(float (&c)[4], const uint32_t (&a)[4],
                                      uint32_t b0, uint32_t b1) {
    asm volatile("mma.sync.aligned.m16n8k16.row.col.f32.f16.f16.f32 "
                 "{%0,%1,%2,%3},{%4,%5,%6,%7},{%8,%9},{%0,%1,%2,%3};"
                 : "+f"(c[0]), "+f"(c[1]), "+f"(c[2]), "+f"(c[3])
                 : "r"(a[0]), "r"(a[1]), "r"(a[2]), "r"(a[3]), "r"(b0), "r"(b1));
}
__device__ __forceinline__ uint32_t sptr(const void* p) {
    return (uint32_t)__cvta_generic_to_shared(p);
}
#define CPA16(dst, src) asm volatile("cp.async.cg.shared.global [%0], [%1], 16;" :: "r"(dst), "l"(src))
#define CP_COMMIT() asm volatile("cp.async.commit_group;")
#define CP_WAIT1() asm volatile("cp.async.wait_group 1;")
#define CP_WAIT0() asm volatile("cp.async.wait_group 0;")

// ---------------- condition projections ----------------
__global__ void ss_kernel(const float* __restrict__ cond,
                          const float* __restrict__ w1, const float* __restrict__ b1,
                          const float* __restrict__ w2, const float* __restrict__ b2) {
    int j = blockIdx.x * blockDim.x + threadIdx.x;
    if (j >= 4 * C) return;
    const float* w = (j < 2 * C) ? w1 : w2;
    const float* b = (j < 2 * C) ? b1 : b2;
    int jj = j & (2 * C - 1);
    float s = 0.f;
    for (int c = 0; c < C; c++) s += cond[c] * w[c * (2 * C) + jj];
    g_ss[j] = s + b[jj];
}

// ---------------- weight pack: W[k][n] fp32 -> wp[k/2][n] half2 ----------------
__global__ __launch_bounds__(256) void wpack_kernel(const float* __restrict__ Wq,
                                                    const float* __restrict__ Wk,
                                                    const float* __restrict__ Wv,
                                                    const float* __restrict__ Wo,
                                                    const float* __restrict__ W1,
                                                    const float* __restrict__ W2) {
    size_t i = ((size_t)blockIdx.x * 256 + threadIdx.x) * 4;   // u32 index
    const float* src; size_t off; int N;
    if (i < U_CC)               { src = Wq; off = i;               N = 512; }
    else if (i < 2 * U_CC)      { src = Wk; off = i - U_CC;        N = 512; }
    else if (i < 3 * U_CC)      { src = Wv; off = i - 2 * U_CC;    N = 512; }
    else if (i < 4 * U_CC)      { src = Wo; off = i - 3 * U_CC;    N = 512; }
    else if (i < 4 * U_CC + U_W1) { src = W1; off = i - 4 * U_CC;  N = 2048; }
    else                        { src = W2; off = i - 4 * U_CC - U_W1; N = 512; }
    size_t kp = off / N; int n = (int)(off % N);
    float4 a = *(const float4*)(src + (2 * kp) * N + n);
    float4 b = *(const float4*)(src + (2 * kp + 1) * N + n);
    uint4 o;
    o.x = packh2(a.x, b.x); o.y = packh2(a.y, b.y);
    o.z = packh2(a.z, b.z); o.w = packh2(a.w, b.w);
    *(uint4*)(g_wp + i) = o;
}

// ---------------- adaLN (half out) ----------------
__global__ __launch_bounds__(256) void adaln_kernel(const float* __restrict__ x,
                                                    const float* __restrict__ g,
                                                    const float* __restrict__ b,
                                                    int ss_off, __half* __restrict__ out) {
    int row = blockIdx.x;
    int t = threadIdx.x;
    const float* xr = x + (size_t)row * C;
    float v0 = xr[t], v1 = xr[t + 256];
    __shared__ float red[256];
    red[t] = v0 + v1;
    __syncthreads();
    for (int s = 128; s > 0; s >>= 1) { if (t < s) red[t] += red[t + s]; __syncthreads(); }
    float mu = red[0] * (1.0f / C);
    __syncthreads();
    float d0 = v0 - mu, d1 = v1 - mu;
    red[t] = d0 * d0 + d1 * d1;
    __syncthreads();
    for (int s = 128; s > 0; s >>= 1) { if (t < s) red[t] += red[t + s]; __syncthreads(); }
    float rs = rsqrtf(red[0] * (1.0f / C) + EPS);
    const float* scale = g_ss + ss_off;
    const float* shift = g_ss + ss_off + C;
    int c0 = t, c1 = t + 256;
    float o0 = (d0 * rs * g[c0] + b[c0]) * (1.f + scale[c0]) + shift[c0];
    float o1 = (d1 * rs * g[c1] + b[c1]) * (1.f + scale[c1]) + shift[c1];
    out[(size_t)row * C + c0] = __float2half_rn(o0);
    out[(size_t)row * C + c1] = __float2half_rn(o1);
}

// ---------------- pair bias precompute (bf16, j written at interleaved slot) ----
__global__ __launch_bounds__(256) void bias_kernel(const float* __restrict__ pair,
                                                   const float* __restrict__ Wpb) {
    __shared__ float w[CZ][H];
    int t = threadIdx.x;
    w[t >> 4][t & 15] = Wpb[t & 255];
    __syncthreads();
    size_t ij = (size_t)blockIdx.x * 256 + t;
    int i = (int)(ij >> 11);
    int j = (int)(ij & (L - 1));
    int slotj = (j & ~15) | ((j & 7) << 1) | ((j >> 3) & 1);
    size_t dstbase = (size_t)i * L + slotj;
    float p[CZ];
    const float* pp = pair + ij * CZ;
    #pragma unroll
    for (int z = 0; z < CZ; z++) p[z] = pp[z];
    #pragma unroll
    for (int h = 0; h < H; h++) {
        float b = 0.f;
        #pragma unroll
        for (int z = 0; z < CZ; z++) b += p[z] * w[z][h];
        g_bias16[(size_t)h * L * L + dstbase] = __float2bfloat16(b);
    }
}

// ---------------- fp16 MMA GEMM, cp.async 2-stage ----------------
// BM=128, BN=NB*16, BK=32 halves (16 pairs). 256 threads = 8 warps (4m x 2n).
// A: half [m][K].  B: packed u32 [K/2][N].
// OUTK: 0 = fp32 out + res,  1 = half2 natural,  2 = V pack ([ch][tokpair])
template <int NB, int HAS_BIAS, int ACT_GELU, int OUTK>
__device__ __forceinline__ void mma_gemm_body(const __half* __restrict__ A,
                                              const uint32_t* __restrict__ B,
                                              const float* __restrict__ bias,
                                              const float* __restrict__ res,
                                              void* __restrict__ Cout,
                                              int N, int K, int bx, int by) {
    const int BN = NB * 16;
    __shared__ uint32_t As[2][128][20];        // 16 data pairs + 4 pad
    __shared__ uint32_t Bs[2][16][BN + 8];
    int t = threadIdx.x;
    int warp = t >> 5, lane = t & 31;
    int wm = warp >> 1, wn = warp & 1;
    int r = lane >> 2, qd = lane & 3;
    int row0 = by * 128, bn0 = bx * BN;

    float acc[2][NB][4];
    #pragma unroll
    for (int mi = 0; mi < 2; mi++)
        #pragma unroll
        for (int nb = 0; nb < NB; nb++)
            #pragma unroll
            for (int e = 0; e < 4; e++) acc[mi][nb][e] = 0.f;

    auto loadTiles = [&](int s, int k0) {      // k0 in halves
        #pragma unroll
        for (int c = 0; c < 2; c++) {
            int ch = t + c * 256;
            int m = ch >> 2, kq = (ch & 3);
            CPA16(sptr(&As[s][m][kq * 4]), A + (size_t)(row0 + m) * K + k0 + kq * 8);
        }
        if (NB == 8) {
            #pragma unroll
            for (int c = 0; c < 2; c++) {
                int ch = t + c * 256;
                int kk = ch >> 5, n4 = (ch & 31) * 4;
                CPA16(sptr(&Bs[s][kk][n4]), B + (size_t)((k0 >> 1) + kk) * N + bn0 + n4);
            }
        } else {
            int kk = t >> 4, n4 = (t & 15) * 4;
            CPA16(sptr(&Bs[s][kk][n4]), B + (size_t)((k0 >> 1) + kk) * N + bn0 + n4);
        }
        CP_COMMIT();
    };

    loadTiles(0, 0);
    int T = K >> 5;
    for (int it = 0; it < T; it++) {
        int s = it & 1;
        if (it + 1 < T) { loadTiles(s ^ 1, (it + 1) << 5); CP_WAIT1(); }
        else            { CP_WAIT0(); }
        __syncthreads();
        #pragma unroll
        for (int kk = 0; kk < 16; kk += 8) {   // pair units, 2 k16 steps
            uint32_t a[2][4];
            #pragma unroll
            for (int mi = 0; mi < 2; mi++) {
                int mo = wm * 32 + mi * 16 + r;
                a[mi][0] = As[s][mo][kk + qd];
                a[mi][1] = As[s][mo + 8][kk + qd];
                a[mi][2] = As[s][mo][kk + qd + 4];
                a[mi][3] = As[s][mo + 8][kk + qd + 4];
            }
            #pragma unroll
            for (int nb = 0; nb < NB; nb++) {
                int nc = wn * NB * 8 + nb * 8 + r;
                uint32_t b0 = Bs[s][kk + qd][nc];
                uint32_t b1 = Bs[s][kk + qd + 4][nc];
                mma16(acc[0][nb], a[0], b0, b1);
                mma16(acc[1][nb], a[1], b0, b1);
            }
        }
        __syncthreads();
    }

    #pragma unroll
    for (int mi = 0; mi < 2; mi++) {
        #pragma unroll
        for (int nb = 0; nb < NB; nb++) {
            int m = row0 + wm * 32 + mi * 16 + r;
            int n = bn0 + wn * NB * 8 + nb * 8 + 2 * qd;
            float v0 = acc[mi][nb][0], v1 = acc[mi][nb][1];
            float v2 = acc[mi][nb][2], v3 = acc[mi][nb][3];
            if (HAS_BIAS) {
                float b0 = bias[n], b1 = bias[n + 1];
                v0 += b0; v1 += b1; v2 += b0; v3 += b1;
            }
            if (ACT_GELU) {
                v0 = 0.5f * v0 * (1.0f + erff(v0 * 0.70710678118654752f));
                v1 = 0.5f * v1 * (1.0f + erff(v1 * 0.70710678118654752f));
                v2 = 0.5f * v2 * (1.0f + erff(v2 * 0.70710678118654752f));
                v3 = 0.5f * v3 * (1.0f + erff(v3 * 0.70710678118654752f));
            }
            if (OUTK == 0) {
                float* Cf = (float*)Cout;
                float2 r0 = *(const float2*)(res + (size_t)m * N + n);
                float2 r1 = *(const float2*)(res + (size_t)(m + 8) * N + n);
                float2 o0 = {v0 + r0.x, v1 + r0.y};
                float2 o1 = {v2 + r1.x, v3 + r1.y};
                *(float2*)(Cf + (size_t)m * N + n) = o0;
                *(float2*)(Cf + (size_t)(m + 8) * N + n) = o1;
            } else if (OUTK == 1) {
                uint32_t* C32 = (uint32_t*)Cout;
                C32[(size_t)m * (N >> 1) + (n >> 1)] = packh2(v0, v1);
                C32[(size_t)(m + 8) * (N >> 1) + (n >> 1)] = packh2(v2, v3);
            } else {
                // V pack: vp[channel][tokpair] = half2(v(tok), v(tok+8))
                uint32_t* V32 = (uint32_t*)Cout;
                int jp = ((m >> 4) << 3) | (m & 7);
                V32[(size_t)n * (L >> 1) + jp] = packh2(v0, v2);
                V32[(size_t)(n + 1) * (L >> 1) + jp] = packh2(v1, v3);
            }
        }
    }
}

__global__ __launch_bounds__(256) void qkv_mma(const __half* __restrict__ hbuf) {
    int sel = blockIdx.x >> 2, bxx = blockIdx.x & 3;
    if (sel == 0)
        mma_gemm_body<8, 0, 0, 1>(hbuf, g_wp, nullptr, nullptr, g_q, C, C, bxx, blockIdx.y);
    else if (sel == 1)
        mma_gemm_body<8, 0, 0, 1>(hbuf, g_wp + U_CC, nullptr, nullptr, g_k, C, C, bxx, blockIdx.y);
    else
        mma_gemm_body<8, 0, 0, 2>(hbuf, g_wp + 2 * U_CC, nullptr, nullptr, g_vp, C, C, bxx, blockIdx.y);
}

__global__ __launch_bounds__(256) void ffn1_mma(const __half* __restrict__ A,
                                                const float* __restrict__ bias) {
    mma_gemm_body<8, 1, 1, 1>(A, g_wp + 4 * U_CC, bias, nullptr, g_ff, 4 * C, C,
                              blockIdx.x, blockIdx.y);
}

__global__ __launch_bounds__(256) void wo_mma(const __half* __restrict__ A,
                                              const float* __restrict__ bias,
                                              const float* __restrict__ res,
                                              float* __restrict__ Cm) {
    mma_gemm_body<4, 1, 0, 0>(A, g_wp + 3 * U_CC, bias, res, Cm, C, C,
                              blockIdx.x, blockIdx.y);
}

__global__ __launch_bounds__(256) void ffn2_mma(const __half* __restrict__ A,
                                                const float* __restrict__ bias,
                                                const float* __restrict__ res,
                                                float* __restrict__ Cm) {
    mma_gemm_body<4, 1, 0, 0>(A, g_wp + 4 * U_CC + U_W1, bias, res, Cm, C, 4 * C,
                              blockIdx.x, blockIdx.y);
}

// ---------------- flash attention (fp16 mma, 128 q-rows, 256 threads) ----------
// smem (bytes):
//   Ks: u32[2][64][20]   @ 0      10240   (K rows at interleaved slots)
//   Vs: u32[2][32][36]   @ 10240   9216   (vp rows: [d][tokpair])
//   Bb: bf16[2][128][72] @ 19456  36864
//   Ps: u32[128][36]     @ 56320  18432
#define FSMEM_BYTES 74752
__global__ __launch_bounds__(256, 2) void flash_kernel(const __half* __restrict__ q,
                                                       const __half* __restrict__ k,
                                                       __half* __restrict__ out) {
    extern __shared__ char fsm[];
    uint32_t* Ks = (uint32_t*)fsm;
    uint32_t* Vs = (uint32_t*)(fsm + 10240);
    __nv_bfloat16* Bb = (__nv_bfloat16*)(fsm + 19456);
    uint32_t* Ps = (uint32_t*)(fsm + 56320);

    int h = blockIdx.y;
    int i0 = blockIdx.x * 128;
    int hD = h * D;
    int t = threadIdx.x;
    int w = t >> 5, lane = t & 31;
    int r = lane >> 2, qd = lane & 3;
    int qrow0 = i0 + w * 16 + r;
    int lr = w * 16 + r;
    const __nv_bfloat16* Bh = g_bias16 + (size_t)h * L * L;
    const uint32_t* q32 = (const uint32_t*)q;

    auto loadKVB = [&](int s, int j0) {
        {   // K rows -> interleaved slots (64 rows x 4 chunks)
            int rw = t >> 2, ch = t & 3;
            int u = rw & 15;
            int srow = (rw & ~15) | ((u & 7) << 1) | (u >> 3);
            CPA16(sptr(Ks + (s * 64 + srow) * 20 + ch * 4),
                  k + (size_t)(j0 + rw) * C + hD + ch * 8);
        }
        {   // V packed rows (32 d x 8 chunks)
            int dd = t >> 3, jc = t & 7;
            CPA16(sptr(Vs + (s * 32 + dd) * 36 + jc * 4),
                  g_vp + (size_t)(hD + dd) * (L >> 1) + (j0 >> 1) + jc * 4);
        }
        #pragma unroll
        for (int c = 0; c < 4; c++) {   // bias (128 rows x 8 chunks)
            int ch = t + c * 256;
            int rw = ch >> 3, e8 = (ch & 7) * 8;
            CPA16(sptr(Bb + (s * 128 + rw) * 72 + e8),
                  Bh + (size_t)(i0 + rw) * L + j0 + e8);
        }
        CP_COMMIT();
    };

    loadKVB(0, 0);

    // Q fragments (natural half pairs along c; 2 k16 steps)
    uint32_t qa[2][4];
    #pragma unroll
    for (int ks = 0; ks < 2; ks++) {
        size_t b0 = (size_t)qrow0 * 256 + h * 16 + ks * 8;
        size_t b1 = (size_t)(qrow0 + 8) * 256 + h * 16 + ks * 8;
        qa[ks][0] = q32[b0 + qd];
        qa[ks][1] = q32[b1 + qd];
        qa[ks][2] = q32[b0 + qd + 4];
        qa[ks][3] = q32[b1 + qd + 4];
    }

    float m0 = -1e30f, m1 = -1e30f, l0 = 0.f, l1 = 0.f;
    float o[4][4];
    #pragma unroll
    for (int nb = 0; nb < 4; nb++)
        #pragma unroll
        for (int e = 0; e < 4; e++) o[nb][e] = 0.f;

    const float sc = 0.17677669529663687f;   // 1/sqrt(32)

    for (int jt = 0; jt < L / 64; jt++) {
        int s = jt & 1;
        if (jt + 1 < L / 64) { loadKVB(s ^ 1, (jt + 1) * 64); CP_WAIT1(); }
        else                 { CP_WAIT0(); }
        __syncthreads();

        // QK^T + bias   (S cols = K slots)
        float sreg[8][4];
        #pragma unroll
        for (int nb = 0; nb < 8; nb++) {
            sreg[nb][0] = sreg[nb][1] = sreg[nb][2] = sreg[nb][3] = 0.f;
            const uint32_t* kr = Ks + (s * 64 + nb * 8 + r) * 20;
            #pragma unroll
            for (int ks = 0; ks < 2; ks++)
                mma16(sreg[nb], qa[ks], kr[ks * 8 + qd], kr[ks * 8 + qd + 4]);
            float2 bb0 = __bfloat1622float2(
                *(const __nv_bfloat162*)&Bb[(s * 128 + lr) * 72 + nb * 8 + 2 * qd]);
            float2 bb1 = __bfloat1622float2(
                *(const __nv_bfloat162*)&Bb[(s * 128 + lr + 8) * 72 + nb * 8 + 2 * qd]);
            sreg[nb][0] = sreg[nb][0] * sc + bb0.x;
            sreg[nb][1] = sreg[nb][1] * sc + bb0.y;
            sreg[nb][2] = sreg[nb][2] * sc + bb1.x;
            sreg[nb][3] = sreg[nb][3] * sc + bb1.y;
        }

        // online softmax (cols are a permutation of j -- invariant)
        float mx0 = -1e30f, mx1 = -1e30f;
        #pragma unroll
        for (int nb = 0; nb < 8; nb++) {
            mx0 = fmaxf(mx0, fmaxf(sreg[nb][0], sreg[nb][1]));
            mx1 = fmaxf(mx1, fmaxf(sreg[nb][2], sreg[nb][3]));
        }
        mx0 = fmaxf(mx0, __shfl_xor_sync(0xffffffffu, mx0, 1));
        mx0 = fmaxf(mx0, __shfl_xor_sync(0xffffffffu, mx0, 2));
        mx1 = fmaxf(mx1, __shfl_xor_sync(0xffffffffu, mx1, 1));
        mx1 = fmaxf(mx1, __shfl_xor_sync(0xffffffffu, mx1, 2));
        float mn0 = fmaxf(m0, mx0), mn1 = fmaxf(m1, mx1);
        float esc0 = __expf(m0 - mn0), esc1 = __expf(m1 - mn1);
        m0 = mn0; m1 = mn1;

        float sum0 = 0.f, sum1 = 0.f;
        #pragma unroll
        for (int nb = 0; nb < 8; nb++) {
            float p0 = __expf(sreg[nb][0] - mn0);
            float p1 = __expf(sreg[nb][1] - mn0);
            float p2 = __expf(sreg[nb][2] - mn1);
            float p3 = __expf(sreg[nb][3] - mn1);
            sum0 += p0 + p1; sum1 += p2 + p3;
            Ps[lr * 36 + nb * 4 + qd] = packh2(p0, p1);
            Ps[(lr + 8) * 36 + nb * 4 + qd] = packh2(p2, p3);
        }
        sum0 += __shfl_xor_sync(0xffffffffu, sum0, 1);
        sum0 += __shfl_xor_sync(0xffffffffu, sum0, 2);
        sum1 += __shfl_xor_sync(0xffffffffu, sum1, 1);
        sum1 += __shfl_xor_sync(0xffffffffu, sum1, 2);
        l0 = l0 * esc0 + sum0;
        l1 = l1 * esc1 + sum1;

        #pragma unroll
        for (int nb = 0; nb < 4; nb++) {
            o[nb][0] *= esc0; o[nb][1] *= esc0;
            o[nb][2] *= esc1; o[nb][3] *= esc1;
        }
        __syncwarp();

        // P @ V  (k = token-pairs; P pairs and V pairs both = (t, t+8))
        #pragma unroll
        for (int ks = 0; ks < 4; ks++) {
            uint32_t pa[4];
            pa[0] = Ps[lr * 36 + ks * 8 + qd];
            pa[1] = Ps[(lr + 8) * 36 + ks * 8 + qd];
            pa[2] = Ps[lr * 36 + ks * 8 + qd + 4];
            pa[3] = Ps[(lr + 8) * 36 + ks * 8 + qd + 4];
            #pragma unroll
            for (int nbd = 0; nbd < 4; nbd++) {
                const uint32_t* vr = Vs + (s * 32 + nbd * 8 + r) * 36;
                mma16(o[nbd], pa, vr[ks * 8 + qd], vr[ks * 8 + qd + 4]);
            }
        }
        __syncthreads();
    }

    float il0 = 1.0f / l0, il1 = 1.0f / l1;
    uint32_t* ao32 = (uint32_t*)out;
    #pragma unroll
    for (int nbd = 0; nbd < 4; nbd++) {
        ao32[(size_t)qrow0 * 256 + h * 16 + nbd * 4 + qd] =
            packh2(o[nbd][0] * il0, o[nbd][1] * il0);
        ao32[(size_t)(qrow0 + 8) * 256 + h * 16 + nbd * 4 + qd] =
            packh2(o[nbd][2] * il1, o[nbd][3] * il1);
    }
}

// ---------------- launch ----------------
extern "C" void kernel_launch(void* const* d_in, const int* in_sizes, int n_in,
                              void* d_out, int out_size) {
    const float* x        = (const float*)d_in[0];
    const float* pair     = (const float*)d_in[1];
    const float* time_cond= (const float*)d_in[2];
    const float* ln1_g    = (const float*)d_in[3];
    const float* ln1_b    = (const float*)d_in[4];
    const float* ada1_w   = (const float*)d_in[5];
    const float* ada1_b   = (const float*)d_in[6];
    const float* Wq       = (const float*)d_in[7];
    const float* Wk       = (const float*)d_in[8];
    const float* Wv       = (const float*)d_in[9];
    const float* Wpb      = (const float*)d_in[10];
    const float* Wo       = (const float*)d_in[11];
    const float* bo       = (const float*)d_in[12];
    const float* ln2_g    = (const float*)d_in[13];
    const float* ln2_b    = (const float*)d_in[14];
    const float* ada2_w   = (const float*)d_in[15];
    const float* ada2_b   = (const float*)d_in[16];
    const float* W1       = (const float*)d_in[17];
    const float* b1       = (const float*)d_in[18];
    const float* W2       = (const float*)d_in[19];
    const float* b2       = (const float*)d_in[20];
    float* out = (float*)d_out;

    __half *p_h, *p_q, *p_k, *p_ao, *p_h2, *p_ff;
    float *p_x1;
    cudaGetSymbolAddress((void**)&p_h,  g_h);
    cudaGetSymbolAddress((void**)&p_q,  g_q);
    cudaGetSymbolAddress((void**)&p_k,  g_k);
    cudaGetSymbolAddress((void**)&p_ao, g_ao);
    cudaGetSymbolAddress((void**)&p_x1, g_x1);
    cudaGetSymbolAddress((void**)&p_h2, g_h2);
    cudaGetSymbolAddress((void**)&p_ff, g_ff);

    static cudaStream_t s1;
    static cudaEvent_t e0, e1;
    static int init_done = 0;
    if (!init_done) {
        cudaFuncSetAttribute(flash_kernel,
                             cudaFuncAttributeMaxDynamicSharedMemorySize, FSMEM_BYTES);
        cudaStreamCreateWithFlags(&s1, cudaStreamNonBlocking);
        cudaEventCreateWithFlags(&e0, cudaEventDisableTiming);
        cudaEventCreateWithFlags(&e1, cudaEventDisableTiming);
        init_done = 1;
    }

    // fork: bias (HBM-bound, independent) overlaps the compute prologue chain
    cudaEventRecord(e0, 0);
    cudaStreamWaitEvent(s1, e0, 0);
    bias_kernel<<<(L * L) / 256, 256, 0, s1>>>(pair, Wpb);
    cudaEventRecord(e1, s1);

    ss_kernel<<<8, 256>>>(time_cond, ada1_w, ada1_b, ada2_w, ada2_b);
    wpack_kernel<<<WP_TOT / 1024, 256>>>(Wq, Wk, Wv, Wo, W1, W2);
    adaln_kernel<<<L, 256>>>(x, ln1_g, ln1_b, 0, p_h);
    qkv_mma<<<dim3(12, 16), 256>>>(p_h);

    // join before flash (needs g_bias16)
    cudaStreamWaitEvent(0, e1, 0);
    flash_kernel<<<dim3(L / 128, H), 256, FSMEM_BYTES>>>(p_q, p_k, p_ao);

    wo_mma<<<dim3(8, 16), 256>>>(p_ao, bo, x, p_x1);
    adaln_kernel<<<L, 256>>>(p_x1, ln2_g, ln2_b, 2 * C, p_h2);
    ffn1_mma<<<dim3(16, 16), 256>>>(p_h2, b1);
    ffn2_mma<<<dim3(8, 16), 256>>>(p_ff, b2, p_x1, out);
}

// round 15
// speedup vs baseline: 1.8168x; 1.4124x over previous
#include <cuda_runtime.h>
#include <cuda_fp16.h>
#include <math.h>
#include <stdint.h>
#include <stddef.h>

#define L 2048
#define C 512
#define CZ 16
#define H 16
#define D 32
#define EPS 1e-5f

// u32 (half2-pair) sizes of packed weights
#define U_CC 131072              // 512*512/2
#define U_W1 524288              // 512*2048/2
#define U_W2 524288              // 2048*512/2
#define WP_TOT (4 * U_CC + U_W1 + U_W2)

// ---------------- scratch ----------------
__device__ float g_ss[4 * C];
__device__ __half g_h[L * C];
__device__ __half g_q[L * C];
__device__ __half g_k[L * C];
__device__ uint32_t g_vp[C * (L / 2)];     // [channel][token-pair] half2 (tok, tok+8)
__device__ uint32_t g_wp[WP_TOT];          // packed weights [k/2][n] half2
__device__ __half g_biash[(size_t)H * L * L];  // fp16 pair bias, slot-permuted j
__device__ __half g_ao[L * C];
__device__ float g_x1[L * C];
__device__ __half g_h2[L * C];
__device__ __half g_ff[L * 4 * C];

// ---------------- helpers ----------------
__device__ __forceinline__ uint32_t packh2(float lo, float hi) {
    __half2 h = __floats2half2_rn(lo, hi);
    return *(uint32_t*)&h;
}
__device__ __forceinline__ void mma16(float (&c)[4], const uint32_t (&a)[4],
                                      uint32_t b0, uint32_t b1) {
    asm volatile("mma.sync.aligned.m16n8k16.row.col.f32.f16.f16.f32 "
                 "{%0,%1,%2,%3},{%4,%5,%6,%7},{%8,%9},{%0,%1,%2,%3};"
                 : "+f"(c[0]), "+f"(c[1]), "+f"(c[2]), "+f"(c[3])
                 : "r"(a[0]), "r"(a[1]), "r"(a[2]), "r"(a[3]), "r"(b0), "r"(b1));
}
__device__ __forceinline__ uint32_t sptr(const void* p) {
    return (uint32_t)__cvta_generic_to_shared(p);
}
#define CPA16(dst, src) asm volatile("cp.async.cg.shared.global [%0], [%1], 16;" :: "r"(dst), "l"(src))
#define CP_COMMIT() asm volatile("cp.async.commit_group;")
#define CP_WAIT1() asm volatile("cp.async.wait_group 1;")
#define CP_WAIT0() asm volatile("cp.async.wait_group 0;")

// ---------------- condition projections ----------------
__global__ void ss_kernel(const float* __restrict__ cond,
                          const float* __restrict__ w1, const float* __restrict__ b1,
                          const float* __restrict__ w2, const float* __restrict__ b2) {
    int j = blockIdx.x * blockDim.x + threadIdx.x;
    if (j >= 4 * C) return;
    const float* w = (j < 2 * C) ? w1 : w2;
    const float* b = (j < 2 * C) ? b1 : b2;
    int jj = j & (2 * C - 1);
    float s = 0.f;
    for (int c = 0; c < C; c++) s += cond[c] * w[c * (2 * C) + jj];
    g_ss[j] = s + b[jj];
}

// ---------------- weight pack: W[k][n] fp32 -> wp[k/2][n] half2 ----------------
__global__ __launch_bounds__(256) void wpack_kernel(const float* __restrict__ Wq,
                                                    const float* __restrict__ Wk,
                                                    const float* __restrict__ Wv,
                                                    const float* __restrict__ Wo,
                                                    const float* __restrict__ W1,
                                                    const float* __restrict__ W2) {
    size_t i = ((size_t)blockIdx.x * 256 + threadIdx.x) * 4;   // u32 index
    const float* src; size_t off; int N;
    if (i < U_CC)               { src = Wq; off = i;               N = 512; }
    else if (i < 2 * U_CC)      { src = Wk; off = i - U_CC;        N = 512; }
    else if (i < 3 * U_CC)      { src = Wv; off = i - 2 * U_CC;    N = 512; }
    else if (i < 4 * U_CC)      { src = Wo; off = i - 3 * U_CC;    N = 512; }
    else if (i < 4 * U_CC + U_W1) { src = W1; off = i - 4 * U_CC;  N = 2048; }
    else                        { src = W2; off = i - 4 * U_CC - U_W1; N = 512; }
    size_t kp = off / N; int n = (int)(off % N);
    float4 a = *(const float4*)(src + (2 * kp) * N + n);
    float4 b = *(const float4*)(src + (2 * kp + 1) * N + n);
    uint4 o;
    o.x = packh2(a.x, b.x); o.y = packh2(a.y, b.y);
    o.z = packh2(a.z, b.z); o.w = packh2(a.w, b.w);
    *(uint4*)(g_wp + i) = o;
}

// ---------------- adaLN (half out, warp-shuffle reductions) ----------------
__global__ __launch_bounds__(256) void adaln_kernel(const float* __restrict__ x,
                                                    const float* __restrict__ g,
                                                    const float* __restrict__ b,
                                                    int ss_off, __half* __restrict__ out) {
    int row = blockIdx.x;
    int t = threadIdx.x;
    const float2* xr = (const float2*)(x + (size_t)row * C);
    float2 v = xr[t];
    __shared__ float red[16];
    float s = v.x + v.y;
    #pragma unroll
    for (int o = 16; o; o >>= 1) s += __shfl_xor_sync(0xffffffffu, s, o);
    if ((t & 31) == 0) red[t >> 5] = s;
    __syncthreads();
    float tot = red[0] + red[1] + red[2] + red[3] + red[4] + red[5] + red[6] + red[7];
    float mu = tot * (1.0f / C);
    float dx = v.x - mu, dy = v.y - mu;
    float q = dx * dx + dy * dy;
    #pragma unroll
    for (int o = 16; o; o >>= 1) q += __shfl_xor_sync(0xffffffffu, q, o);
    if ((t & 31) == 0) red[8 + (t >> 5)] = q;
    __syncthreads();
    float var = (red[8] + red[9] + red[10] + red[11] +
                 red[12] + red[13] + red[14] + red[15]) * (1.0f / C);
    float rs = rsqrtf(var + EPS);
    float2 gg = ((const float2*)g)[t];
    float2 bb = ((const float2*)b)[t];
    float2 sc2 = ((const float2*)(g_ss + ss_off))[t];
    float2 sh2 = ((const float2*)(g_ss + ss_off + C))[t];
    float o0 = (dx * rs * gg.x + bb.x) * (1.f + sc2.x) + sh2.x;
    float o1 = (dy * rs * gg.y + bb.y) * (1.f + sc2.y) + sh2.y;
    ((__half2*)out)[(size_t)row * 256 + t] = __floats2half2_rn(o0, o1);
}

// ---------------- pair bias: HFMA2 compute, fp16 out, slot-permuted u32 pack ----
// block: 256 threads = 256 token-pairs = 512 j (one i row segment).
// thread t: group g = t>>3, m = t&7; tokens j_a = j0+g*16+m, j_b = j_a+8.
// packed u32 (j_a, j_b) lands at u32 index g*8+m == slot-permuted layout.
__global__ __launch_bounds__(256) void bias_kernel(const float* __restrict__ pair,
                                                   const float* __restrict__ Wpb) {
    __shared__ __half2 w2[CZ][8];
    __shared__ uint32_t bs[16][256];
    int t = threadIdx.x;
    if (t < 128) {
        int z = t >> 3, hp = t & 7;
        w2[z][hp] = __floats2half2_rn(Wpb[z * H + 2 * hp], Wpb[z * H + 2 * hp + 1]);
    }
    int i = blockIdx.x >> 2;
    int j0 = (blockIdx.x & 3) * 512;
    int gg = t >> 3, m = t & 7;
    size_t ij_a = (size_t)i * L + j0 + gg * 16 + m;
    size_t ij_b = ij_a + 8;
    float4 pa[4], pb[4];
    #pragma unroll
    for (int c = 0; c < 4; c++) {
        pa[c] = *(const float4*)(pair + ij_a * CZ + c * 4);
        pb[c] = *(const float4*)(pair + ij_b * CZ + c * 4);
    }
    __syncthreads();
    __half2 acc_a[8], acc_b[8];
    #pragma unroll
    for (int hp = 0; hp < 8; hp++) { acc_a[hp] = __half2(0, 0); acc_b[hp] = __half2(0, 0); }
    const float* fa = (const float*)pa;
    const float* fb = (const float*)pb;
    #pragma unroll
    for (int z = 0; z < CZ; z++) {
        __half2 va = __floats2half2_rn(fa[z], fa[z]);
        __half2 vb = __floats2half2_rn(fb[z], fb[z]);
        #pragma unroll
        for (int hp = 0; hp < 8; hp++) {
            acc_a[hp] = __hfma2(va, w2[z][hp], acc_a[hp]);
            acc_b[hp] = __hfma2(vb, w2[z][hp], acc_b[hp]);
        }
    }
    #pragma unroll
    for (int hp = 0; hp < 8; hp++) {
        __half2 lo = __lows2half2(acc_a[hp], acc_b[hp]);    // h = 2hp
        __half2 hi = __highs2half2(acc_a[hp], acc_b[hp]);   // h = 2hp+1
        bs[2 * hp][t] = *(uint32_t*)&lo;
        bs[2 * hp + 1][t] = *(uint32_t*)&hi;
    }
    __syncthreads();
    uint32_t* out32 = (uint32_t*)g_biash;
    #pragma unroll
    for (int c = 0; c < 4; c++) {
        int ch = t + c * 256;
        int h = ch >> 6, p4 = (ch & 63) * 4;
        uint4 val = *(const uint4*)&bs[h][p4];
        *(uint4*)(out32 + (size_t)h * (L * L / 2) + (size_t)i * (L / 2) + (j0 >> 1) + p4) = val;
    }
}

// ---------------- fp16 MMA GEMM, cp.async 2-stage ----------------
// BM=128, BN=NB*16, BK=32 halves (16 pairs). 256 threads = 8 warps (4m x 2n).
// A: half [m][K].  B: packed u32 [K/2][N].
// OUTK: 0 = fp32 out + res,  1 = half2 natural,  2 = V pack ([ch][tokpair])
template <int NB, int HAS_BIAS, int ACT_GELU, int OUTK>
__device__ __forceinline__ void mma_gemm_body(const __half* __restrict__ A,
                                              const uint32_t* __restrict__ B,
                                              const float* __restrict__ bias,
                                              const float* __restrict__ res,
                                              void* __restrict__ Cout,
                                              int N, int K, int bx, int by) {
    const int BN = NB * 16;
    __shared__ uint32_t As[2][128][20];        // 16 data pairs + 4 pad
    __shared__ uint32_t Bs[2][16][BN + 8];
    int t = threadIdx.x;
    int warp = t >> 5, lane = t & 31;
    int wm = warp >> 1, wn = warp & 1;
    int r = lane >> 2, qd = lane & 3;
    int row0 = by * 128, bn0 = bx * BN;

    float acc[2][NB][4];
    #pragma unroll
    for (int mi = 0; mi < 2; mi++)
        #pragma unroll
        for (int nb = 0; nb < NB; nb++)
            #pragma unroll
            for (int e = 0; e < 4; e++) acc[mi][nb][e] = 0.f;

    auto loadTiles = [&](int s, int k0) {      // k0 in halves
        #pragma unroll
        for (int c = 0; c < 2; c++) {
            int ch = t + c * 256;
            int m = ch >> 2, kq = (ch & 3);
            CPA16(sptr(&As[s][m][kq * 4]), A + (size_t)(row0 + m) * K + k0 + kq * 8);
        }
        if (NB == 8) {
            #pragma unroll
            for (int c = 0; c < 2; c++) {
                int ch = t + c * 256;
                int kk = ch >> 5, n4 = (ch & 31) * 4;
                CPA16(sptr(&Bs[s][kk][n4]), B + (size_t)((k0 >> 1) + kk) * N + bn0 + n4);
            }
        } else {
            int kk = t >> 4, n4 = (t & 15) * 4;
            CPA16(sptr(&Bs[s][kk][n4]), B + (size_t)((k0 >> 1) + kk) * N + bn0 + n4);
        }
        CP_COMMIT();
    };

    loadTiles(0, 0);
    int T = K >> 5;
    for (int it = 0; it < T; it++) {
        int s = it & 1;
        if (it + 1 < T) { loadTiles(s ^ 1, (it + 1) << 5); CP_WAIT1(); }
        else            { CP_WAIT0(); }
        __syncthreads();
        #pragma unroll
        for (int kk = 0; kk < 16; kk += 8) {   // pair units, 2 k16 steps
            uint32_t a[2][4];
            #pragma unroll
            for (int mi = 0; mi < 2; mi++) {
                int mo = wm * 32 + mi * 16 + r;
                a[mi][0] = As[s][mo][kk + qd];
                a[mi][1] = As[s][mo + 8][kk + qd];
                a[mi][2] = As[s][mo][kk + qd + 4];
                a[mi][3] = As[s][mo + 8][kk + qd + 4];
            }
            #pragma unroll
            for (int nb = 0; nb < NB; nb++) {
                int nc = wn * NB * 8 + nb * 8 + r;
                uint32_t b0 = Bs[s][kk + qd][nc];
                uint32_t b1 = Bs[s][kk + qd + 4][nc];
                mma16(acc[0][nb], a[0], b0, b1);
                mma16(acc[1][nb], a[1], b0, b1);
            }
        }
        __syncthreads();
    }

    #pragma unroll
    for (int mi = 0; mi < 2; mi++) {
        #pragma unroll
        for (int nb = 0; nb < NB; nb++) {
            int m = row0 + wm * 32 + mi * 16 + r;
            int n = bn0 + wn * NB * 8 + nb * 8 + 2 * qd;
            float v0 = acc[mi][nb][0], v1 = acc[mi][nb][1];
            float v2 = acc[mi][nb][2], v3 = acc[mi][nb][3];
            if (HAS_BIAS) {
                float b0 = bias[n], b1 = bias[n + 1];
                v0 += b0; v1 += b1; v2 += b0; v3 += b1;
            }
            if (ACT_GELU) {
                v0 = 0.5f * v0 * (1.0f + erff(v0 * 0.70710678118654752f));
                v1 = 0.5f * v1 * (1.0f + erff(v1 * 0.70710678118654752f));
                v2 = 0.5f * v2 * (1.0f + erff(v2 * 0.70710678118654752f));
                v3 = 0.5f * v3 * (1.0f + erff(v3 * 0.70710678118654752f));
            }
            if (OUTK == 0) {
                float* Cf = (float*)Cout;
                float2 r0 = *(const float2*)(res + (size_t)m * N + n);
                float2 r1 = *(const float2*)(res + (size_t)(m + 8) * N + n);
                float2 o0 = {v0 + r0.x, v1 + r0.y};
                float2 o1 = {v2 + r1.x, v3 + r1.y};
                *(float2*)(Cf + (size_t)m * N + n) = o0;
                *(float2*)(Cf + (size_t)(m + 8) * N + n) = o1;
            } else if (OUTK == 1) {
                uint32_t* C32 = (uint32_t*)Cout;
                C32[(size_t)m * (N >> 1) + (n >> 1)] = packh2(v0, v1);
                C32[(size_t)(m + 8) * (N >> 1) + (n >> 1)] = packh2(v2, v3);
            } else {
                // V pack: vp[channel][tokpair] = half2(v(tok), v(tok+8))
                uint32_t* V32 = (uint32_t*)Cout;
                int jp = ((m >> 4) << 3) | (m & 7);
                V32[(size_t)n * (L >> 1) + jp] = packh2(v0, v2);
                V32[(size_t)(n + 1) * (L >> 1) + jp] = packh2(v1, v3);
            }
        }
    }
}

__global__ __launch_bounds__(256) void qkv_mma(const __half* __restrict__ hbuf) {
    int sel = blockIdx.x >> 2, bxx = blockIdx.x & 3;
    if (sel == 0)
        mma_gemm_body<8, 0, 0, 1>(hbuf, g_wp, nullptr, nullptr, g_q, C, C, bxx, blockIdx.y);
    else if (sel == 1)
        mma_gemm_body<8, 0, 0, 1>(hbuf, g_wp + U_CC, nullptr, nullptr, g_k, C, C, bxx, blockIdx.y);
    else
        mma_gemm_body<8, 0, 0, 2>(hbuf, g_wp + 2 * U_CC, nullptr, nullptr, g_vp, C, C, bxx, blockIdx.y);
}

__global__ __launch_bounds__(256) void ffn1_mma(const __half* __restrict__ A,
                                                const float* __restrict__ bias) {
    mma_gemm_body<8, 1, 1, 1>(A, g_wp + 4 * U_CC, bias, nullptr, g_ff, 4 * C, C,
                              blockIdx.x, blockIdx.y);
}

__global__ __launch_bounds__(256) void wo_mma(const __half* __restrict__ A,
                                              const float* __restrict__ bias,
                                              const float* __restrict__ res,
                                              float* __restrict__ Cm) {
    mma_gemm_body<4, 1, 0, 0>(A, g_wp + 3 * U_CC, bias, res, Cm, C, C,
                              blockIdx.x, blockIdx.y);
}

__global__ __launch_bounds__(256) void ffn2_mma(const __half* __restrict__ A,
                                                const float* __restrict__ bias,
                                                const float* __restrict__ res,
                                                float* __restrict__ Cm) {
    mma_gemm_body<4, 1, 0, 0>(A, g_wp + 4 * U_CC + U_W1, bias, res, Cm, C, 4 * C,
                              blockIdx.x, blockIdx.y);
}

// ---------------- flash attention (fp16 mma, 128 q-rows, 256 threads) ----------
// smem (bytes):
//   Ks: u32[2][64][20]   @ 0      10240   (K rows at interleaved slots)
//   Vs: u32[2][32][36]   @ 10240   9216   (vp rows: [d][tokpair])
//   Bb: half[2][128][72] @ 19456  36864
//   Ps: u32[128][36]     @ 56320  18432
#define FSMEM_BYTES 74752
__global__ __launch_bounds__(256, 2) void flash_kernel(const __half* __restrict__ q,
                                                       const __half* __restrict__ k,
                                                       __half* __restrict__ out) {
    extern __shared__ char fsm[];
    uint32_t* Ks = (uint32_t*)fsm;
    uint32_t* Vs = (uint32_t*)(fsm + 10240);
    __half* Bb = (__half*)(fsm + 19456);
    uint32_t* Ps = (uint32_t*)(fsm + 56320);

    int h = blockIdx.y;
    int i0 = blockIdx.x * 128;
    int hD = h * D;
    int t = threadIdx.x;
    int w = t >> 5, lane = t & 31;
    int r = lane >> 2, qd = lane & 3;
    int qrow0 = i0 + w * 16 + r;
    int lr = w * 16 + r;
    const __half* Bh = g_biash + (size_t)h * L * L;
    const uint32_t* q32 = (const uint32_t*)q;

    auto loadKVB = [&](int s, int j0) {
        {   // K rows -> interleaved slots (64 rows x 4 chunks)
            int rw = t >> 2, ch = t & 3;
            int u = rw & 15;
            int srow = (rw & ~15) | ((u & 7) << 1) | (u >> 3);
            CPA16(sptr(Ks + (s * 64 + srow) * 20 + ch * 4),
                  k + (size_t)(j0 + rw) * C + hD + ch * 8);
        }
        {   // V packed rows (32 d x 8 chunks)
            int dd = t >> 3, jc = t & 7;
            CPA16(sptr(Vs + (s * 32 + dd) * 36 + jc * 4),
                  g_vp + (size_t)(hD + dd) * (L >> 1) + (j0 >> 1) + jc * 4);
        }
        #pragma unroll
        for (int c = 0; c < 4; c++) {   // bias (128 rows x 8 chunks)
            int ch = t + c * 256;
            int rw = ch >> 3, e8 = (ch & 7) * 8;
            CPA16(sptr(Bb + (s * 128 + rw) * 72 + e8),
                  Bh + (size_t)(i0 + rw) * L + j0 + e8);
        }
        CP_COMMIT();
    };

    loadKVB(0, 0);

    // Q fragments (natural half pairs along c; 2 k16 steps)
    uint32_t qa[2][4];
    #pragma unroll
    for (int ks = 0; ks < 2; ks++) {
        size_t b0 = (size_t)qrow0 * 256 + h * 16 + ks * 8;
        size_t b1 = (size_t)(qrow0 + 8) * 256 + h * 16 + ks * 8;
        qa[ks][0] = q32[b0 + qd];
        qa[ks][1] = q32[b1 + qd];
        qa[ks][2] = q32[b0 + qd + 4];
        qa[ks][3] = q32[b1 + qd + 4];
    }

    float m0 = -1e30f, m1 = -1e30f, l0 = 0.f, l1 = 0.f;
    float o[4][4];
    #pragma unroll
    for (int nb = 0; nb < 4; nb++)
        #pragma unroll
        for (int e = 0; e < 4; e++) o[nb][e] = 0.f;

    const float sc = 0.17677669529663687f;   // 1/sqrt(32)
    const float L2E = 1.4426950408889634f;

    for (int jt = 0; jt < L / 64; jt++) {
        int s = jt & 1;
        if (jt + 1 < L / 64) { loadKVB(s ^ 1, (jt + 1) * 64); CP_WAIT1(); }
        else                 { CP_WAIT0(); }
        __syncthreads();

        // QK^T + bias   (S cols = K slots)
        float sreg[8][4];
        #pragma unroll
        for (int nb = 0; nb < 8; nb++) {
            sreg[nb][0] = sreg[nb][1] = sreg[nb][2] = sreg[nb][3] = 0.f;
            const uint32_t* kr = Ks + (s * 64 + nb * 8 + r) * 20;
            #pragma unroll
            for (int ks = 0; ks < 2; ks++)
                mma16(sreg[nb], qa[ks], kr[ks * 8 + qd], kr[ks * 8 + qd + 4]);
            float2 bb0 = __half22float2(
                *(const __half2*)&Bb[(s * 128 + lr) * 72 + nb * 8 + 2 * qd]);
            float2 bb1 = __half22float2(
                *(const __half2*)&Bb[(s * 128 + lr + 8) * 72 + nb * 8 + 2 * qd]);
            sreg[nb][0] = sreg[nb][0] * sc + bb0.x;
            sreg[nb][1] = sreg[nb][1] * sc + bb0.y;
            sreg[nb][2] = sreg[nb][2] * sc + bb1.x;
            sreg[nb][3] = sreg[nb][3] * sc + bb1.y;
        }

        // online softmax (cols are a permutation of j -- invariant)
        float mx0 = -1e30f, mx1 = -1e30f;
        #pragma unroll
        for (int nb = 0; nb < 8; nb++) {
            mx0 = fmaxf(mx0, fmaxf(sreg[nb][0], sreg[nb][1]));
            mx1 = fmaxf(mx1, fmaxf(sreg[nb][2], sreg[nb][3]));
        }
        mx0 = fmaxf(mx0, __shfl_xor_sync(0xffffffffu, mx0, 1));
        mx0 = fmaxf(mx0, __shfl_xor_sync(0xffffffffu, mx0, 2));
        mx1 = fmaxf(mx1, __shfl_xor_sync(0xffffffffu, mx1, 1));
        mx1 = fmaxf(mx1, __shfl_xor_sync(0xffffffffu, mx1, 2));
        float mn0 = fmaxf(m0, mx0), mn1 = fmaxf(m1, mx1);
        float esc0 = __expf(m0 - mn0), esc1 = __expf(m1 - mn1);
        m0 = mn0; m1 = mn1;

        // exp via f16x2 MUFU: p = 2^((s - mn) * log2e)
        float mb0 = mn0 * L2E, mb1 = mn1 * L2E;
        float sum0 = 0.f, sum1 = 0.f;
        #pragma unroll
        for (int nb = 0; nb < 8; nb++) {
            float t0 = fmaf(sreg[nb][0], L2E, -mb0);
            float t1 = fmaf(sreg[nb][1], L2E, -mb0);
            float t2 = fmaf(sreg[nb][2], L2E, -mb1);
            float t3 = fmaf(sreg[nb][3], L2E, -mb1);
            __half2 e01 = h2exp2(__floats2half2_rn(t0, t1));
            __half2 e23 = h2exp2(__floats2half2_rn(t2, t3));
            Ps[lr * 36 + nb * 4 + qd] = *(uint32_t*)&e01;
            Ps[(lr + 8) * 36 + nb * 4 + qd] = *(uint32_t*)&e23;
            float2 f01 = __half22float2(e01);
            float2 f23 = __half22float2(e23);
            sum0 += f01.x + f01.y;
            sum1 += f23.x + f23.y;
        }
        sum0 += __shfl_xor_sync(0xffffffffu, sum0, 1);
        sum0 += __shfl_xor_sync(0xffffffffu, sum0, 2);
        sum1 += __shfl_xor_sync(0xffffffffu, sum1, 1);
        sum1 += __shfl_xor_sync(0xffffffffu, sum1, 2);
        l0 = l0 * esc0 + sum0;
        l1 = l1 * esc1 + sum1;

        #pragma unroll
        for (int nb = 0; nb < 4; nb++) {
            o[nb][0] *= esc0; o[nb][1] *= esc0;
            o[nb][2] *= esc1; o[nb][3] *= esc1;
        }
        __syncwarp();

        // P @ V  (k = token-pairs; P pairs and V pairs both = (t, t+8))
        #pragma unroll
        for (int ks = 0; ks < 4; ks++) {
            uint32_t pa[4];
            pa[0] = Ps[lr * 36 + ks * 8 + qd];
            pa[1] = Ps[(lr + 8) * 36 + ks * 8 + qd];
            pa[2] = Ps[lr * 36 + ks * 8 + qd + 4];
            pa[3] = Ps[(lr + 8) * 36 + ks * 8 + qd + 4];
            #pragma unroll
            for (int nbd = 0; nbd < 4; nbd++) {
                const uint32_t* vr = Vs + (s * 32 + nbd * 8 + r) * 36;
                mma16(o[nbd], pa, vr[ks * 8 + qd], vr[ks * 8 + qd + 4]);
            }
        }
        __syncthreads();
    }

    float il0 = 1.0f / l0, il1 = 1.0f / l1;
    uint32_t* ao32 = (uint32_t*)out;
    #pragma unroll
    for (int nbd = 0; nbd < 4; nbd++) {
        ao32[(size_t)qrow0 * 256 + h * 16 + nbd * 4 + qd] =
            packh2(o[nbd][0] * il0, o[nbd][1] * il0);
        ao32[(size_t)(qrow0 + 8) * 256 + h * 16 + nbd * 4 + qd] =
            packh2(o[nbd][2] * il1, o[nbd][3] * il1);
    }
}

// ---------------- launch ----------------
extern "C" void kernel_launch(void* const* d_in, const int* in_sizes, int n_in,
                              void* d_out, int out_size) {
    const float* x        = (const float*)d_in[0];
    const float* pair     = (const float*)d_in[1];
    const float* time_cond= (const float*)d_in[2];
    const float* ln1_g    = (const float*)d_in[3];
    const float* ln1_b    = (const float*)d_in[4];
    const float* ada1_w   = (const float*)d_in[5];
    const float* ada1_b   = (const float*)d_in[6];
    const float* Wq       = (const float*)d_in[7];
    const float* Wk       = (const float*)d_in[8];
    const float* Wv       = (const float*)d_in[9];
    const float* Wpb      = (const float*)d_in[10];
    const float* Wo       = (const float*)d_in[11];
    const float* bo       = (const float*)d_in[12];
    const float* ln2_g    = (const float*)d_in[13];
    const float* ln2_b    = (const float*)d_in[14];
    const float* ada2_w   = (const float*)d_in[15];
    const float* ada2_b   = (const float*)d_in[16];
    const float* W1       = (const float*)d_in[17];
    const float* b1       = (const float*)d_in[18];
    const float* W2       = (const float*)d_in[19];
    const float* b2       = (const float*)d_in[20];
    float* out = (float*)d_out;

    __half *p_h, *p_q, *p_k, *p_ao, *p_h2, *p_ff;
    float *p_x1;
    cudaGetSymbolAddress((void**)&p_h,  g_h);
    cudaGetSymbolAddress((void**)&p_q,  g_q);
    cudaGetSymbolAddress((void**)&p_k,  g_k);
    cudaGetSymbolAddress((void**)&p_ao, g_ao);
    cudaGetSymbolAddress((void**)&p_x1, g_x1);
    cudaGetSymbolAddress((void**)&p_h2, g_h2);
    cudaGetSymbolAddress((void**)&p_ff, g_ff);

    static cudaStream_t s1;
    static cudaEvent_t e0, e1;
    static int init_done = 0;
    if (!init_done) {
        cudaFuncSetAttribute(flash_kernel,
                             cudaFuncAttributeMaxDynamicSharedMemorySize, FSMEM_BYTES);
        cudaStreamCreateWithFlags(&s1, cudaStreamNonBlocking);
        cudaEventCreateWithFlags(&e0, cudaEventDisableTiming);
        cudaEventCreateWithFlags(&e1, cudaEventDisableTiming);
        init_done = 1;
    }

    // fork: bias (HBM/HFMA2, independent) overlaps the compute prologue chain
    cudaEventRecord(e0, 0);
    cudaStreamWaitEvent(s1, e0, 0);
    bias_kernel<<<(L * L) / 512, 256, 0, s1>>>(pair, Wpb);
    cudaEventRecord(e1, s1);

    ss_kernel<<<8, 256>>>(time_cond, ada1_w, ada1_b, ada2_w, ada2_b);
    wpack_kernel<<<WP_TOT / 1024, 256>>>(Wq, Wk, Wv, Wo, W1, W2);
    adaln_kernel<<<L, 256>>>(x, ln1_g, ln1_b, 0, p_h);
    qkv_mma<<<dim3(12, 16), 256>>>(p_h);

    // join before flash (needs g_biash)
    cudaStreamWaitEvent(0, e1, 0);
    flash_kernel<<<dim3(L / 128, H), 256, FSMEM_BYTES>>>(p_q, p_k, p_ao);

    wo_mma<<<dim3(8, 16), 256>>>(p_ao, bo, x, p_x1);
    adaln_kernel<<<L, 256>>>(p_x1, ln2_g, ln2_b, 2 * C, p_h2);
    ffn1_mma<<<dim3(16, 16), 256>>>(p_h2, b1);
    ffn2_mma<<<dim3(8, 16), 256>>>(p_ff, b2, p_x1, out);
}